// round 2
// baseline (speedup 1.0000x reference)
#include <cuda_runtime.h>
#include <cuda_bf16.h>
#include <math.h>

// ---------------------------------------------------------------------------
// Problem constants
// ---------------------------------------------------------------------------
#define Bv    32
#define NCLS  20
#define Tt    2048
#define Dd    2048
#define Ll    128
#define NPAIR 16
#define GAMMA_F 0.1f
#define INV_GAMMA_F 10.0f
#define THRES_F 0.5f

// ---------------------------------------------------------------------------
// Device scratch (no allocations allowed)
// ---------------------------------------------------------------------------
// rnorm tensors: 0=lcs full, 1=act first half, 2=act second half,
//                3=bak first half, 4=bak second half   (each [32*128])
__device__ float g_rnorm[5 * Bv * Ll];
__device__ float g_sim_lcs[32 * Ll * Ll];   // transformed s for LCS DP
__device__ float g_sim_m[32 * Ll * Ll];     // FSD m
__device__ float g_sim_g[32 * Ll * Ll];     // FSD g
// partial sums: 0 cls, 1 guide, 2 feat, 3 sparse, 4 posLCS, 5 negLCS,
//               6 act_act, 7 act_bak
__device__ float g_partial[8];

// ---------------------------------------------------------------------------
// init: zero the partial accumulators
// ---------------------------------------------------------------------------
__global__ void k_init() {
    if (threadIdx.x < 8) g_partial[threadIdx.x] = 0.0f;
}

// ---------------------------------------------------------------------------
// row reciprocal norms: warp per row
// ---------------------------------------------------------------------------
__global__ void k_norms(const float* __restrict__ lcs,
                        const float* __restrict__ act,
                        const float* __restrict__ bak) {
    int warp = (blockIdx.x * blockDim.x + threadIdx.x) >> 5;
    int lane = threadIdx.x & 31;
    const int ROWS = Bv * Ll;                 // 4096
    if (warp >= 5 * ROWS) return;
    int tensor = warp / ROWS;
    int r      = warp % ROWS;

    const float* base; int off, len;
    switch (tensor) {
        case 0: base = lcs; off = 0;    len = 2048; break;
        case 1: base = act; off = 0;    len = 1024; break;
        case 2: base = act; off = 1024; len = 1024; break;
        case 3: base = bak; off = 0;    len = 1024; break;
        default: base = bak; off = 1024; len = 1024; break;
    }
    const float* p = base + (size_t)r * Dd + off;
    float s = 0.0f;
    for (int k = lane * 4; k < len; k += 128) {
        float4 v = *(const float4*)(p + k);
        s += v.x * v.x + v.y * v.y + v.z * v.z + v.w * v.w;
    }
#pragma unroll
    for (int o = 16; o > 0; o >>= 1)
        s += __shfl_xor_sync(0xffffffffu, s, o);
    if (lane == 0) g_rnorm[tensor * ROWS + r] = rsqrtf(s);
}

// ---------------------------------------------------------------------------
// Similarity GEMMs.  96 sims: [0,32) LCS (K=2048), [32,96) FSD m/g (K=1024).
// Block = one 128x64 output tile (2 blocks per sim). 256 threads.
// BM=128, BN=64, BK=16, TM=8, TN=4.
// ---------------------------------------------------------------------------
#define BM 128
#define BN 64
#define BK 16

__global__ __launch_bounds__(256, 2)
void k_gemm(const float* __restrict__ lcs,
            const float* __restrict__ act,
            const float* __restrict__ bak,
            const int* __restrict__ pos,
            const int* __restrict__ neg) {
    int blk = blockIdx.x;           // 0..191
    int sim = blk >> 1;
    int colTile = (blk & 1) * BN;

    const float *Abase, *Bbase, *rnA, *rnB;
    float* out;
    int Ksteps;
    int do_transform;

    if (sim < 32) {
        int p  = sim;
        int i0 = (p < 16) ? pos[2 * p]     : neg[2 * (p - 16)];
        int i1 = (p < 16) ? pos[2 * p + 1] : neg[2 * (p - 16) + 1];
        Abase = lcs + (size_t)i0 * Ll * Dd;
        Bbase = lcs + (size_t)i1 * Ll * Dd;
        rnA = g_rnorm + 0 * (Bv * Ll) + i0 * Ll;
        rnB = g_rnorm + 0 * (Bv * Ll) + i1 * Ll;
        out = g_sim_lcs + (size_t)p * Ll * Ll;
        Ksteps = 2048 / BK;
        do_transform = 1;
    } else {
        int f = sim - 32;
        int p = f >> 1;
        int half = f & 1;
        int i0 = (p < 16) ? pos[2 * p]     : neg[2 * (p - 16)];
        int i1 = (p < 16) ? pos[2 * p + 1] : neg[2 * (p - 16) + 1];
        Abase = act + (size_t)i0 * Ll * Dd + half * 1024;
        rnA = g_rnorm + (1 + half) * (Bv * Ll) + i0 * Ll;
        if (p < 16) {
            Bbase = act + (size_t)i1 * Ll * Dd + half * 1024;
            rnB = g_rnorm + (1 + half) * (Bv * Ll) + i1 * Ll;
        } else {
            Bbase = bak + (size_t)i1 * Ll * Dd + half * 1024;
            rnB = g_rnorm + (3 + half) * (Bv * Ll) + i1 * Ll;
        }
        out = (half ? g_sim_g : g_sim_m) + (size_t)p * Ll * Ll;
        Ksteps = 1024 / BK;
        do_transform = 0;
    }
    Bbase += (size_t)colTile * Dd;

    __shared__ float As[BK][BM];   // [k][m]
    __shared__ float Bs[BK][BN];   // [k][n]

    int t  = threadIdx.x;
    int tx = t & 15;               // 0..15 -> cols tx*4
    int ty = t >> 4;               // 0..15 -> rows ty*8

    float acc[8][4];
#pragma unroll
    for (int i = 0; i < 8; ++i)
#pragma unroll
        for (int j = 0; j < 4; ++j) acc[i][j] = 0.0f;

    for (int kt = 0; kt < Ksteps; ++kt) {
        int k0 = kt * BK;
        // load A: 128 rows x 16 k = 512 float4, 2 per thread
#pragma unroll
        for (int it = 0; it < 2; ++it) {
            int s   = t + it * 256;
            int row = s >> 2;
            int kc  = (s & 3) * 4;
            float4 v = *(const float4*)(Abase + (size_t)row * Dd + k0 + kc);
            As[kc + 0][row] = v.x;
            As[kc + 1][row] = v.y;
            As[kc + 2][row] = v.z;
            As[kc + 3][row] = v.w;
        }
        // load B: 64 rows x 16 k = 256 float4, 1 per thread
        {
            int row = t >> 2;
            int kc  = (t & 3) * 4;
            float4 v = *(const float4*)(Bbase + (size_t)row * Dd + k0 + kc);
            Bs[kc + 0][row] = v.x;
            Bs[kc + 1][row] = v.y;
            Bs[kc + 2][row] = v.z;
            Bs[kc + 3][row] = v.w;
        }
        __syncthreads();

#pragma unroll
        for (int k = 0; k < BK; ++k) {
            float4 a0 = *(const float4*)&As[k][ty * 8];
            float4 a1 = *(const float4*)&As[k][ty * 8 + 4];
            float4 b0 = *(const float4*)&Bs[k][tx * 4];
            float av[8] = {a0.x, a0.y, a0.z, a0.w, a1.x, a1.y, a1.z, a1.w};
            float bv[4] = {b0.x, b0.y, b0.z, b0.w};
#pragma unroll
            for (int i = 0; i < 8; ++i)
#pragma unroll
                for (int j = 0; j < 4; ++j)
                    acc[i][j] = fmaf(av[i], bv[j], acc[i][j]);
        }
        __syncthreads();
    }

    float ra[8], rb[4];
#pragma unroll
    for (int i = 0; i < 8; ++i) ra[i] = rnA[ty * 8 + i];
#pragma unroll
    for (int j = 0; j < 4; ++j) rb[j] = rnB[colTile + tx * 4 + j];

#pragma unroll
    for (int i = 0; i < 8; ++i) {
        int row = ty * 8 + i;
#pragma unroll
        for (int j = 0; j < 4; ++j) {
            int col = colTile + tx * 4 + j;
            float v = acc[i][j] * ra[i] * rb[j];
            if (do_transform) v = fmaxf(0.0f, v - 0.8f) * 5.0f;
            out[row * Ll + col] = v;
        }
    }
}

// ---------------------------------------------------------------------------
// LCS wavefront DP. One block (128 threads) per pair. smem: S[128*128] + C[129*130]
// ---------------------------------------------------------------------------
__global__ void k_lcs_dp() {
    extern __shared__ float sm[];
    float* S = sm;                  // 16384
    float* C = sm + Ll * Ll;        // 129*130

    int p = blockIdx.x;
    int t = threadIdx.x;            // 0..127
    const float* src = g_sim_lcs + (size_t)p * Ll * Ll;
    for (int idx = t * 4; idx < Ll * Ll; idx += 512)
        *(float4*)(S + idx) = *(const float4*)(src + idx);

    // boundaries
    C[t] = 0.0f;
    if (t == 0) C[128] = 0.0f;
    C[(t + 1) * 130] = 0.0f;
    __syncthreads();

    int i = t + 1;
    for (int d = 2; d <= 2 * Ll; ++d) {
        if (i >= d - Ll && i <= d - 1) {
            int j = d - i;
            float s  = S[(i - 1) * Ll + (j - 1)];
            float cd = C[(i - 1) * 130 + (j - 1)];
            float cu = C[(i - 1) * 130 + j];
            float cl = C[i * 130 + (j - 1)];
            float nv = (s > THRES_F) ? (cd + s) : fmaxf(cu, cl);
            C[i * 130 + j] = nv;
        }
        __syncthreads();
    }
    if (t == 127)
        atomicAdd(&g_partial[p < 16 ? 4 : 5], C[128 * 130 + 128]);
}

// ---------------------------------------------------------------------------
// FSD soft-DP. One block per pair. smem: M + G + C
// ---------------------------------------------------------------------------
__global__ void k_fsd_dp() {
    extern __shared__ float sm[];
    float* M = sm;                         // 16384
    float* G = sm + Ll * Ll;               // 16384
    float* C = sm + 2 * Ll * Ll;           // 129*130

    int p = blockIdx.x;
    int t = threadIdx.x;
    const float* msrc = g_sim_m + (size_t)p * Ll * Ll;
    const float* gsrc = g_sim_g + (size_t)p * Ll * Ll;
    for (int idx = t * 4; idx < Ll * Ll; idx += 512) {
        *(float4*)(M + idx) = *(const float4*)(msrc + idx);
        *(float4*)(G + idx) = *(const float4*)(gsrc + idx);
    }
    C[t] = 0.0f;
    if (t == 0) C[128] = 0.0f;
    C[(t + 1) * 130] = 0.0f;
    __syncthreads();

    int i = t + 1;
    for (int d = 2; d <= 2 * Ll; ++d) {
        if (i >= d - Ll && i <= d - 1) {
            int j = d - i;
            float mv = M[(i - 1) * Ll + (j - 1)];
            float gv = G[(i - 1) * Ll + (j - 1)];
            float cd = C[(i - 1) * 130 + (j - 1)];
            float cu = C[(i - 1) * 130 + j];
            float cl = C[i * 130 + (j - 1)];
            float x1 = gv + cu;
            float x2 = gv + cl;
            float mx = fmaxf(cd, fmaxf(x1, x2));
            float ss = __expf((cd - mx) * INV_GAMMA_F)
                     + __expf((x1 - mx) * INV_GAMMA_F)
                     + __expf((x2 - mx) * INV_GAMMA_F);
            C[i * 130 + j] = mv + mx + GAMMA_F * __logf(ss);
        }
        __syncthreads();
    }
    if (t == 127)
        atomicAdd(&g_partial[p < 16 ? 6 : 7], C[128 * 130 + 128]);
}

// ---------------------------------------------------------------------------
// Small ACM losses. One block per batch element.
// ---------------------------------------------------------------------------
__global__ void k_small(const float* __restrict__ xi,   // act_inst_cls [32,21]
                        const float* __restrict__ xc,   // act_cont_cls
                        const float* __restrict__ xb,   // act_back_cls
                        const float* __restrict__ vid,  // [32,20]
                        const float* __restrict__ att,  // [32,2048,3]
                        const float* __restrict__ fi,   // act_inst_feat [32,2048]
                        const float* __restrict__ fc,
                        const float* __restrict__ fb,
                        const float* __restrict__ cas)  // [32,2048,21]
{
    __shared__ float red[256];
    int b = blockIdx.x;
    int tid = threadIdx.x;

    float guide = 0.0f, sparse = 0.0f, si2 = 0.0f, sc2 = 0.0f, sb2 = 0.0f;
    for (int tt = tid; tt < Tt; tt += 256) {
        float cas20 = cas[((size_t)b * Tt + tt) * (NCLS + 1) + NCLS];
        float a0 = att[((size_t)b * Tt + tt) * 3 + 0];
        float a1 = att[((size_t)b * Tt + tt) * 3 + 1];
        guide  += fabsf(1.0f - cas20 - a0);
        sparse += a0 + a1;
    }
    for (int k = tid; k < Dd; k += 256) {
        float vi = fi[(size_t)b * Dd + k];
        float vc = fc[(size_t)b * Dd + k];
        float vb = fb[(size_t)b * Dd + k];
        si2 += vi * vi; sc2 += vc * vc; sb2 += vb * vb;
    }

    float vals[5] = {guide, sparse, si2, sc2, sb2};
#pragma unroll
    for (int v = 0; v < 5; ++v) {
        red[tid] = vals[v];
        __syncthreads();
        for (int s = 128; s > 0; s >>= 1) {
            if (tid < s) red[tid] += red[tid + s];
            __syncthreads();
        }
        vals[v] = red[0];
        __syncthreads();
    }

    if (tid == 0) {
        float ni = sqrtf(vals[2]);
        float nc = sqrtf(vals[3]);
        float nb = sqrtf(vals[4]);
        float f1 = fmaxf(50.0f - ni + nc, 0.0f);
        float f2 = fmaxf(50.0f - nc + nb, 0.0f);
        float feat = (f1 + f2 + nb) * (f1 + f2 + nb);

        // cls
        float sv = 0.0f, s_i = 0.0f, s_c = 0.0f;
        for (int c = 0; c < NCLS; ++c) {
            float l = vid[b * NCLS + c];
            sv  += l;
            s_i += l * logf(xi[b * (NCLS + 1) + c] + 1e-45f);
            s_c += l * logf(xc[b * (NCLS + 1) + c] + 1e-45f);
        }
        float inst_b = -s_i / sv;
        float cont_b = -(s_c + logf(xc[b * (NCLS + 1) + NCLS] + 1e-45f)) / (sv + 1.0f);
        float back_b = -logf(xb[b * (NCLS + 1) + NCLS] + 1e-45f);
        float cls_b = inst_b + cont_b + back_b;

        atomicAdd(&g_partial[0], cls_b);
        atomicAdd(&g_partial[1], vals[0]);
        atomicAdd(&g_partial[2], feat);
        atomicAdd(&g_partial[3], vals[1]);
    }
}

// ---------------------------------------------------------------------------
// Combine
// ---------------------------------------------------------------------------
__global__ void k_combine(float* out) {
    float cls    = g_partial[0] / 32.0f;
    float guide  = g_partial[1] / 32.0f;
    float feat   = g_partial[2] / 32.0f;
    float sparse = g_partial[3] / 64.0f;
    float acm = cls + 1.0f * guide + 5e-5f * feat + 2e-4f * sparse;
    float lcs_loss = (g_partial[5] - g_partial[4]) / 16.0f;
    float fsd_loss = (g_partial[7] - g_partial[6]) / 16.0f;
    out[0] = acm + 0.1f * lcs_loss + 0.1f * fsd_loss;
}

// ---------------------------------------------------------------------------
// Launch
// ---------------------------------------------------------------------------
extern "C" void kernel_launch(void* const* d_in, const int* in_sizes, int n_in,
                              void* d_out, int out_size) {
    const float* xi  = (const float*)d_in[0];
    const float* xc  = (const float*)d_in[1];
    const float* xb  = (const float*)d_in[2];
    const float* vid = (const float*)d_in[3];
    const float* att = (const float*)d_in[4];
    const float* fi  = (const float*)d_in[5];
    const float* fc  = (const float*)d_in[6];
    const float* fb  = (const float*)d_in[7];
    const float* cas = (const float*)d_in[8];
    const float* lcs = (const float*)d_in[9];
    const float* act = (const float*)d_in[10];
    const float* bak = (const float*)d_in[11];
    const int*   pos = (const int*)d_in[12];
    const int*   neg = (const int*)d_in[13];
    float* out = (float*)d_out;

    const int lcs_smem = (Ll * Ll + 129 * 130) * (int)sizeof(float);       // ~132.6 KB
    const int fsd_smem = (2 * Ll * Ll + 129 * 130) * (int)sizeof(float);   // ~198.2 KB
    cudaFuncSetAttribute(k_lcs_dp, cudaFuncAttributeMaxDynamicSharedMemorySize, lcs_smem);
    cudaFuncSetAttribute(k_fsd_dp, cudaFuncAttributeMaxDynamicSharedMemorySize, fsd_smem);

    k_init<<<1, 32>>>();
    // 5 tensors x 4096 rows = 20480 warps; 8 warps/block
    k_norms<<<2560, 256>>>(lcs, act, bak);
    k_gemm<<<192, 256>>>(lcs, act, bak, pos, neg);
    k_fsd_dp<<<32, 128, fsd_smem>>>();
    k_lcs_dp<<<32, 128, lcs_smem>>>();
    k_small<<<32, 256>>>(xi, xc, xb, vid, att, fi, fc, fb, cas);
    k_combine<<<1, 1>>>(out);
}

// round 4
// speedup vs baseline: 1.7301x; 1.7301x over previous
#include <cuda_runtime.h>
#include <cuda_bf16.h>
#include <stdint.h>
#include <math.h>

// ---------------------------------------------------------------------------
// Problem constants
// ---------------------------------------------------------------------------
#define Bv    32
#define NCLS  20
#define Tt    2048
#define Dd    2048
#define Ll    128

// ---------------------------------------------------------------------------
// Device scratch
// ---------------------------------------------------------------------------
__device__ float g_rnorm[5 * Bv * Ll];
__device__ float g_sim_lcs[32 * Ll * Ll];
__device__ float g_sim_m[32 * Ll * Ll];
__device__ float g_sim_g[32 * Ll * Ll];
// 0 cls, 1 guide, 2 feat, 3 sparse, 4 posLCS, 5 negLCS, 6 act_act, 7 act_bak
__device__ float g_partial[8];

__global__ void k_init() {
    if (threadIdx.x < 8) g_partial[threadIdx.x] = 0.0f;
}

// ---------------------------------------------------------------------------
// row reciprocal norms: warp per row
// ---------------------------------------------------------------------------
__global__ void k_norms(const float* __restrict__ lcs,
                        const float* __restrict__ act,
                        const float* __restrict__ bak) {
    int warp = (blockIdx.x * blockDim.x + threadIdx.x) >> 5;
    int lane = threadIdx.x & 31;
    const int ROWS = Bv * Ll;
    if (warp >= 5 * ROWS) return;
    int tensor = warp / ROWS;
    int r      = warp % ROWS;

    const float* base; int off, len;
    switch (tensor) {
        case 0: base = lcs; off = 0;    len = 2048; break;
        case 1: base = act; off = 0;    len = 1024; break;
        case 2: base = act; off = 1024; len = 1024; break;
        case 3: base = bak; off = 0;    len = 1024; break;
        default: base = bak; off = 1024; len = 1024; break;
    }
    const float* p = base + (size_t)r * Dd + off;
    float s = 0.0f;
    for (int k = lane * 4; k < len; k += 128) {
        float4 v = *(const float4*)(p + k);
        s += v.x * v.x + v.y * v.y + v.z * v.z + v.w * v.w;
    }
#pragma unroll
    for (int o = 16; o > 0; o >>= 1)
        s += __shfl_xor_sync(0xffffffffu, s, o);
    if (lane == 0) g_rnorm[tensor * ROWS + r] = rsqrtf(s);
}

// ---------------------------------------------------------------------------
// bf16 tensor-core GEMM.  192 blocks: sim = blk>>1, colTile = (blk&1)*64.
// BM=128, BN=64, BK=32.  256 threads = 8 warps (4 m x 2 n), warp = 32x32.
// fp32 global -> bf16 smem conversion on the fly; epilogue normalizes.
// ---------------------------------------------------------------------------
__device__ __forceinline__ uint32_t swz(uint32_t row, uint32_t col) {
    // row*64B + swizzled 16B chunk + byte-in-chunk
    return row * 64u + ((((col >> 3) ^ ((row >> 1) & 3u)) << 4)) + ((col & 7u) << 1);
}

__device__ __forceinline__ uint32_t pk_bf2(float lo, float hi) {
    __nv_bfloat162 h = __floats2bfloat162_rn(lo, hi);
    return *(uint32_t*)&h;
}

__device__ __forceinline__ void ldsm4(uint32_t addr, uint32_t& r0, uint32_t& r1,
                                      uint32_t& r2, uint32_t& r3) {
    asm volatile("ldmatrix.sync.aligned.m8n8.x4.shared.b16 {%0,%1,%2,%3}, [%4];"
                 : "=r"(r0), "=r"(r1), "=r"(r2), "=r"(r3) : "r"(addr));
}

__device__ __forceinline__ void mma16816(float* c, const uint32_t* a,
                                         uint32_t b0, uint32_t b1) {
    asm volatile("mma.sync.aligned.m16n8k16.row.col.f32.bf16.bf16.f32 "
                 "{%0,%1,%2,%3}, {%4,%5,%6,%7}, {%8,%9}, {%0,%1,%2,%3};"
                 : "+f"(c[0]), "+f"(c[1]), "+f"(c[2]), "+f"(c[3])
                 : "r"(a[0]), "r"(a[1]), "r"(a[2]), "r"(a[3]), "r"(b0), "r"(b1));
}

__global__ __launch_bounds__(256, 2)
void k_gemm(const float* __restrict__ lcs,
            const float* __restrict__ act,
            const float* __restrict__ bak,
            const int* __restrict__ pos,
            const int* __restrict__ neg) {
    int blk = blockIdx.x;           // 0..191
    int sim = blk >> 1;
    int colTile = (blk & 1) * 64;

    const float *Abase, *Bbase, *rnA, *rnB;
    float* out;
    int Ksteps;
    int do_transform;

    if (sim < 32) {
        int p  = sim;
        int i0 = (p < 16) ? pos[2 * p]     : neg[2 * (p - 16)];
        int i1 = (p < 16) ? pos[2 * p + 1] : neg[2 * (p - 16) + 1];
        Abase = lcs + (size_t)i0 * Ll * Dd;
        Bbase = lcs + (size_t)i1 * Ll * Dd;
        rnA = g_rnorm + 0 * (Bv * Ll) + i0 * Ll;
        rnB = g_rnorm + 0 * (Bv * Ll) + i1 * Ll;
        out = g_sim_lcs + (size_t)p * Ll * Ll;
        Ksteps = 2048 / 32;
        do_transform = 1;
    } else {
        int f = sim - 32;
        int p = f >> 1;
        int half = f & 1;
        int i0 = (p < 16) ? pos[2 * p]     : neg[2 * (p - 16)];
        int i1 = (p < 16) ? pos[2 * p + 1] : neg[2 * (p - 16) + 1];
        Abase = act + (size_t)i0 * Ll * Dd + half * 1024;
        rnA = g_rnorm + (1 + half) * (Bv * Ll) + i0 * Ll;
        if (p < 16) {
            Bbase = act + (size_t)i1 * Ll * Dd + half * 1024;
            rnB = g_rnorm + (1 + half) * (Bv * Ll) + i1 * Ll;
        } else {
            Bbase = bak + (size_t)i1 * Ll * Dd + half * 1024;
            rnB = g_rnorm + (3 + half) * (Bv * Ll) + i1 * Ll;
        }
        out = (half ? g_sim_g : g_sim_m) + (size_t)p * Ll * Ll;
        Ksteps = 1024 / 32;
        do_transform = 0;
    }
    Bbase += (size_t)colTile * Dd;

    // smem: A 128 rows x 64B (8KB), B 64 rows x 64B (4KB)
    __shared__ uint4 smBuf[(128 * 64 + 64 * 64) / 16];
    char* smc = (char*)smBuf;
    uint32_t smemBase = (uint32_t)__cvta_generic_to_shared(smc);

    int tid  = threadIdx.x;
    int lane = tid & 31;
    int warp = tid >> 5;
    int wm = warp >> 1;             // 0..3
    int wn = warp & 1;              // 0..1

    // loader indices
    int aRow0 = tid >> 2,            aKg0 = tid & 3;           // idx = tid
    int aRow1 = (tid + 256) >> 2,    aKg1 = tid & 3;           // idx = tid+256
    int bRow  = tid >> 2,            bKg  = tid & 3;           // 64 rows x 4 kg

    float acc[2][4][4];
#pragma unroll
    for (int i = 0; i < 2; ++i)
#pragma unroll
        for (int j = 0; j < 4; ++j)
#pragma unroll
            for (int q = 0; q < 4; ++q) acc[i][j][q] = 0.0f;

    float4 bufA[2][2], bufB[2];

    // preload chunk 0
    {
        const float* p0 = Abase + (size_t)aRow0 * Dd + aKg0 * 8;
        bufA[0][0] = *(const float4*)(p0);
        bufA[0][1] = *(const float4*)(p0 + 4);
        const float* p1 = Abase + (size_t)aRow1 * Dd + aKg1 * 8;
        bufA[1][0] = *(const float4*)(p1);
        bufA[1][1] = *(const float4*)(p1 + 4);
        const float* pb = Bbase + (size_t)bRow * Dd + bKg * 8;
        bufB[0] = *(const float4*)(pb);
        bufB[1] = *(const float4*)(pb + 4);
    }

    // ldmatrix address components (constant per thread)
    int grp = lane >> 3, r8 = lane & 7;
    uint32_t aRowL = (uint32_t)(r8 + (grp & 1) * 8);      // + m0
    uint32_t aColL = (uint32_t)((grp >> 1) * 8);          // + k0
    uint32_t bRowL = (uint32_t)(r8 + (grp >> 1) * 8);     // + n0
    uint32_t bColL = (uint32_t)((grp & 1) * 8);           // + k0

    for (int kt = 0; kt < Ksteps; ++kt) {
        // STS (convert fp32 regs -> bf16 smem)
        {
            uint4 v;
            v.x = pk_bf2(bufA[0][0].x, bufA[0][0].y);
            v.y = pk_bf2(bufA[0][0].z, bufA[0][0].w);
            v.z = pk_bf2(bufA[0][1].x, bufA[0][1].y);
            v.w = pk_bf2(bufA[0][1].z, bufA[0][1].w);
            *(uint4*)(smc + swz(aRow0, aKg0 * 8)) = v;
            v.x = pk_bf2(bufA[1][0].x, bufA[1][0].y);
            v.y = pk_bf2(bufA[1][0].z, bufA[1][0].w);
            v.z = pk_bf2(bufA[1][1].x, bufA[1][1].y);
            v.w = pk_bf2(bufA[1][1].z, bufA[1][1].w);
            *(uint4*)(smc + swz(aRow1, aKg1 * 8)) = v;
            v.x = pk_bf2(bufB[0].x, bufB[0].y);
            v.y = pk_bf2(bufB[0].z, bufB[0].w);
            v.z = pk_bf2(bufB[1].x, bufB[1].y);
            v.w = pk_bf2(bufB[1].z, bufB[1].w);
            *(uint4*)(smc + 8192 + swz(bRow, bKg * 8)) = v;
        }
        __syncthreads();

        // prefetch next chunk (overlaps with MMA below)
        if (kt + 1 < Ksteps) {
            int k0 = (kt + 1) * 32;
            const float* p0 = Abase + (size_t)aRow0 * Dd + k0 + aKg0 * 8;
            bufA[0][0] = *(const float4*)(p0);
            bufA[0][1] = *(const float4*)(p0 + 4);
            const float* p1 = Abase + (size_t)aRow1 * Dd + k0 + aKg1 * 8;
            bufA[1][0] = *(const float4*)(p1);
            bufA[1][1] = *(const float4*)(p1 + 4);
            const float* pb = Bbase + (size_t)bRow * Dd + k0 + bKg * 8;
            bufB[0] = *(const float4*)(pb);
            bufB[1] = *(const float4*)(pb + 4);
        }

        // compute 2 x k16 steps
#pragma unroll
        for (int ks = 0; ks < 2; ++ks) {
            int k0 = ks * 16;
            uint32_t afr[2][4];
#pragma unroll
            for (int tm = 0; tm < 2; ++tm) {
                uint32_t m0 = (uint32_t)(wm * 32 + tm * 16);
                uint32_t addrA = smemBase + swz(m0 + aRowL, (uint32_t)k0 + aColL);
                ldsm4(addrA, afr[tm][0], afr[tm][1], afr[tm][2], afr[tm][3]);
            }
            uint32_t bfr[2][4];
#pragma unroll
            for (int tb = 0; tb < 2; ++tb) {
                uint32_t n0 = (uint32_t)(wn * 32 + tb * 16);
                uint32_t addrB = smemBase + 8192u + swz(n0 + bRowL, (uint32_t)k0 + bColL);
                ldsm4(addrB, bfr[tb][0], bfr[tb][1], bfr[tb][2], bfr[tb][3]);
            }
#pragma unroll
            for (int tm = 0; tm < 2; ++tm)
#pragma unroll
                for (int tn = 0; tn < 4; ++tn) {
                    int tb = tn >> 1, wh = tn & 1;
                    mma16816(acc[tm][tn], afr[tm], bfr[tb][wh * 2], bfr[tb][wh * 2 + 1]);
                }
        }
        __syncthreads();
    }

    // epilogue: normalize, optional LCS transform, store
    int g8 = lane >> 2, tq = lane & 3;
#pragma unroll
    for (int tm = 0; tm < 2; ++tm) {
        int row0 = wm * 32 + tm * 16 + g8;
        int row1 = row0 + 8;
        float ra0 = rnA[row0], ra1 = rnA[row1];
#pragma unroll
        for (int tn = 0; tn < 4; ++tn) {
            int col = colTile + wn * 32 + tn * 8 + 2 * tq;
            float rb0 = rnB[col], rb1 = rnB[col + 1];
            float v00 = acc[tm][tn][0] * ra0 * rb0;
            float v01 = acc[tm][tn][1] * ra0 * rb1;
            float v10 = acc[tm][tn][2] * ra1 * rb0;
            float v11 = acc[tm][tn][3] * ra1 * rb1;
            if (do_transform) {
                v00 = fmaxf(0.0f, v00 - 0.8f) * 5.0f;
                v01 = fmaxf(0.0f, v01 - 0.8f) * 5.0f;
                v10 = fmaxf(0.0f, v10 - 0.8f) * 5.0f;
                v11 = fmaxf(0.0f, v11 - 0.8f) * 5.0f;
            }
            *(float2*)(out + row0 * Ll + col) = make_float2(v00, v01);
            *(float2*)(out + row1 * Ll + col) = make_float2(v10, v11);
        }
    }
}

// ---------------------------------------------------------------------------
// Warp-wavefront DP: one warp per DP, thread owns 4 rows (transposed view,
// valid since both recurrences are symmetric under transpose).
// blocks 0..31 = FSD pairs, 32..63 = LCS pairs. No barriers in the loop.
// ---------------------------------------------------------------------------
__device__ __forceinline__ float fsd_cell(float m, float g, float cd, float cu, float cl) {
    float x1 = g + cu, x2 = g + cl;
    float mx = fmaxf(cd, fmaxf(x1, x2));
    float ss = __expf((cd - mx) * 10.0f) + __expf((x1 - mx) * 10.0f)
             + __expf((x2 - mx) * 10.0f);
    return m + mx + 0.1f * __logf(ss);
}

__device__ __forceinline__ float lcs_cell(float s, float cd, float cu, float cl) {
    return (s > 0.5f) ? (cd + s) : fmaxf(cu, cl);
}

__global__ void k_dp() {
    int b = blockIdx.x;
    bool isFsd = (b < 32);
    int pair = isFsd ? b : b - 32;
    const float* Mb = (isFsd ? g_sim_m : g_sim_lcs) + (size_t)pair * Ll * Ll;
    const float* Gb = g_sim_g + (size_t)pair * Ll * Ll;

    int t = threadIdx.x;               // 0..31, owns rows 4t..4t+3 (transposed)
    float cl0 = 0.f, cl1 = 0.f, cl2 = 0.f, cl3 = 0.f;
    float last = 0.f;                  // last-row value at current col
    float diag_up = 0.f;               // C[4t][j-1]

    float4 mc, mn, gc, gn;
    gc = make_float4(0.f, 0.f, 0.f, 0.f);
    gn = gc;
    mc = *(const float4*)(Mb + 0 * Ll + 4 * t);
    mn = *(const float4*)(Mb + 1 * Ll + 4 * t);
    if (isFsd) {
        gc = *(const float4*)(Gb + 0 * Ll + 4 * t);
        gn = *(const float4*)(Gb + 1 * Ll + 4 * t);
    }

    for (int s = 0; s < 2 * Ll - 1 + 32; ++s) {   // s in [0, 158]
        float fu = __shfl_up_sync(0xffffffffu, last, 1);
        if (t == 0) fu = 0.f;
        int c = s - t;                  // matrix row (j-1)
        if (c >= 0 && c < Ll) {
            float4 m4 = mc, g4 = gc;
            mc = mn; gc = gn;
            int cn = c + 2;
            if (cn < Ll) {
                mn = *(const float4*)(Mb + cn * Ll + 4 * t);
                if (isFsd) gn = *(const float4*)(Gb + cn * Ll + 4 * t);
            }
            float nv0, nv1, nv2, nv3;
            if (isFsd) {
                nv0 = fsd_cell(m4.x, g4.x, diag_up, fu, cl0);
                nv1 = fsd_cell(m4.y, g4.y, cl0, nv0, cl1);
                nv2 = fsd_cell(m4.z, g4.z, cl1, nv1, cl2);
                nv3 = fsd_cell(m4.w, g4.w, cl2, nv2, cl3);
            } else {
                nv0 = lcs_cell(m4.x, diag_up, fu, cl0);
                nv1 = lcs_cell(m4.y, cl0, nv0, cl1);
                nv2 = lcs_cell(m4.z, cl1, nv1, cl2);
                nv3 = lcs_cell(m4.w, cl2, nv2, cl3);
            }
            cl0 = nv0; cl1 = nv1; cl2 = nv2; cl3 = nv3;
            last = nv3;
            diag_up = fu;
        }
    }
    if (t == 31) {
        int slot = isFsd ? (pair < 16 ? 6 : 7) : (pair < 16 ? 4 : 5);
        atomicAdd(&g_partial[slot], cl3);
    }
}

// ---------------------------------------------------------------------------
// Small ACM losses. One block per batch element.
// ---------------------------------------------------------------------------
__global__ void k_small(const float* __restrict__ xi,
                        const float* __restrict__ xc,
                        const float* __restrict__ xb,
                        const float* __restrict__ vid,
                        const float* __restrict__ att,
                        const float* __restrict__ fi,
                        const float* __restrict__ fc,
                        const float* __restrict__ fb,
                        const float* __restrict__ cas)
{
    __shared__ float red[256];
    int b = blockIdx.x;
    int tid = threadIdx.x;

    float guide = 0.0f, sparse = 0.0f, si2 = 0.0f, sc2 = 0.0f, sb2 = 0.0f;
    for (int tt = tid; tt < Tt; tt += 256) {
        float cas20 = cas[((size_t)b * Tt + tt) * (NCLS + 1) + NCLS];
        float a0 = att[((size_t)b * Tt + tt) * 3 + 0];
        float a1 = att[((size_t)b * Tt + tt) * 3 + 1];
        guide  += fabsf(1.0f - cas20 - a0);
        sparse += a0 + a1;
    }
    for (int k = tid; k < Dd; k += 256) {
        float vi = fi[(size_t)b * Dd + k];
        float vc = fc[(size_t)b * Dd + k];
        float vb = fb[(size_t)b * Dd + k];
        si2 += vi * vi; sc2 += vc * vc; sb2 += vb * vb;
    }

    float vals[5] = {guide, sparse, si2, sc2, sb2};
#pragma unroll
    for (int v = 0; v < 5; ++v) {
        red[tid] = vals[v];
        __syncthreads();
        for (int s = 128; s > 0; s >>= 1) {
            if (tid < s) red[tid] += red[tid + s];
            __syncthreads();
        }
        vals[v] = red[0];
        __syncthreads();
    }

    if (tid == 0) {
        float ni = sqrtf(vals[2]);
        float nc = sqrtf(vals[3]);
        float nb = sqrtf(vals[4]);
        float f1 = fmaxf(50.0f - ni + nc, 0.0f);
        float f2 = fmaxf(50.0f - nc + nb, 0.0f);
        float feat = (f1 + f2 + nb) * (f1 + f2 + nb);

        float sv = 0.0f, s_i = 0.0f, s_c = 0.0f;
        for (int c = 0; c < NCLS; ++c) {
            float l = vid[b * NCLS + c];
            sv  += l;
            s_i += l * logf(xi[b * (NCLS + 1) + c] + 1e-45f);
            s_c += l * logf(xc[b * (NCLS + 1) + c] + 1e-45f);
        }
        float inst_b = -s_i / sv;
        float cont_b = -(s_c + logf(xc[b * (NCLS + 1) + NCLS] + 1e-45f)) / (sv + 1.0f);
        float back_b = -logf(xb[b * (NCLS + 1) + NCLS] + 1e-45f);
        float cls_b = inst_b + cont_b + back_b;

        atomicAdd(&g_partial[0], cls_b);
        atomicAdd(&g_partial[1], vals[0]);
        atomicAdd(&g_partial[2], feat);
        atomicAdd(&g_partial[3], vals[1]);
    }
}

__global__ void k_combine(float* out) {
    float cls    = g_partial[0] / 32.0f;
    float guide  = g_partial[1] / 32.0f;
    float feat   = g_partial[2] / 32.0f;
    float sparse = g_partial[3] / 64.0f;
    float acm = cls + 1.0f * guide + 5e-5f * feat + 2e-4f * sparse;
    float lcs_loss = (g_partial[5] - g_partial[4]) / 16.0f;
    float fsd_loss = (g_partial[7] - g_partial[6]) / 16.0f;
    out[0] = acm + 0.1f * lcs_loss + 0.1f * fsd_loss;
}

// ---------------------------------------------------------------------------
// Launch
// ---------------------------------------------------------------------------
extern "C" void kernel_launch(void* const* d_in, const int* in_sizes, int n_in,
                              void* d_out, int out_size) {
    const float* xi  = (const float*)d_in[0];
    const float* xc  = (const float*)d_in[1];
    const float* xb  = (const float*)d_in[2];
    const float* vid = (const float*)d_in[3];
    const float* att = (const float*)d_in[4];
    const float* fi  = (const float*)d_in[5];
    const float* fc  = (const float*)d_in[6];
    const float* fb  = (const float*)d_in[7];
    const float* cas = (const float*)d_in[8];
    const float* lcs = (const float*)d_in[9];
    const float* act = (const float*)d_in[10];
    const float* bak = (const float*)d_in[11];
    const int*   pos = (const int*)d_in[12];
    const int*   neg = (const int*)d_in[13];
    float* out = (float*)d_out;

    k_init<<<1, 32>>>();
    k_norms<<<2560, 256>>>(lcs, act, bak);
    k_gemm<<<192, 256>>>(lcs, act, bak, pos, neg);
    k_dp<<<64, 32>>>();
    k_small<<<32, 256>>>(xi, xc, xb, vid, att, fi, fc, fb, cas);
    k_combine<<<1, 1>>>(out);
}

// round 5
// speedup vs baseline: 1.9718x; 1.1397x over previous
#include <cuda_runtime.h>
#include <cuda_bf16.h>
#include <stdint.h>
#include <math.h>

#define Bv    32
#define NCLS  20
#define Tt    2048
#define Dd    2048
#define Ll    128

// FSD scale: 10 * log2(e)  (gamma=0.1 -> work in log2 x10 domain)
#define FSD_SCALE 14.426950408889634f
// back: ln(2)/10
#define FSD_UNSCALE 0.06931471805599453f

// ---------------------------------------------------------------------------
// Device scratch
// ---------------------------------------------------------------------------
__device__ float g_sim_lcs[32 * Ll * Ll];   // transformed LCS s
__device__ float g_sim_m[32 * Ll * Ll];     // FSD m (x FSD_SCALE)
__device__ float g_sim_g[32 * Ll * Ll];     // FSD g (x FSD_SCALE)
// 0 cls, 1 guide, 2 feat, 3 sparse, 4 posLCS, 5 negLCS, 6 act_act, 7 act_bak
__device__ float g_partial[8];

__global__ void k_init() {
    if (threadIdx.x < 8) g_partial[threadIdx.x] = 0.0f;
}

// ---------------------------------------------------------------------------
// bf16 tensor-core GEMM with fused row-norm computation.
// 192 blocks: sim = blk>>1, colTile = (blk&1)*64.
// BM=128, BN=64, BK=32. 256 threads = 8 warps (4m x 2n), warp tile 32x32.
// ---------------------------------------------------------------------------
__device__ __forceinline__ uint32_t swz(uint32_t row, uint32_t col) {
    return row * 64u + ((((col >> 3) ^ ((row >> 1) & 3u)) << 4)) + ((col & 7u) << 1);
}

__device__ __forceinline__ uint32_t pk_bf2(float lo, float hi) {
    __nv_bfloat162 h = __floats2bfloat162_rn(lo, hi);
    return *(uint32_t*)&h;
}

__device__ __forceinline__ void ldsm4(uint32_t addr, uint32_t& r0, uint32_t& r1,
                                      uint32_t& r2, uint32_t& r3) {
    asm volatile("ldmatrix.sync.aligned.m8n8.x4.shared.b16 {%0,%1,%2,%3}, [%4];"
                 : "=r"(r0), "=r"(r1), "=r"(r2), "=r"(r3) : "r"(addr));
}

__device__ __forceinline__ void mma16816(float* c, const uint32_t* a,
                                         uint32_t b0, uint32_t b1) {
    asm volatile("mma.sync.aligned.m16n8k16.row.col.f32.bf16.bf16.f32 "
                 "{%0,%1,%2,%3}, {%4,%5,%6,%7}, {%8,%9}, {%0,%1,%2,%3};"
                 : "+f"(c[0]), "+f"(c[1]), "+f"(c[2]), "+f"(c[3])
                 : "r"(a[0]), "r"(a[1]), "r"(a[2]), "r"(a[3]), "r"(b0), "r"(b1));
}

__global__ __launch_bounds__(256, 2)
void k_gemm(const float* __restrict__ lcs,
            const float* __restrict__ act,
            const float* __restrict__ bak,
            const int* __restrict__ pos,
            const int* __restrict__ neg) {
    int blk = blockIdx.x;           // 0..191
    int sim = blk >> 1;
    int colTile = (blk & 1) * 64;

    const float *Abase, *Bbase;
    float* out;
    int Ksteps;
    int mode;   // 0 = FSD (scale), 1 = LCS (transform)

    if (sim < 32) {
        int p  = sim;
        int i0 = (p < 16) ? pos[2 * p]     : neg[2 * (p - 16)];
        int i1 = (p < 16) ? pos[2 * p + 1] : neg[2 * (p - 16) + 1];
        Abase = lcs + (size_t)i0 * Ll * Dd;
        Bbase = lcs + (size_t)i1 * Ll * Dd;
        out = g_sim_lcs + (size_t)p * Ll * Ll;
        Ksteps = 2048 / 32;
        mode = 1;
    } else {
        int f = sim - 32;
        int p = f >> 1;
        int half = f & 1;
        int i0 = (p < 16) ? pos[2 * p]     : neg[2 * (p - 16)];
        int i1 = (p < 16) ? pos[2 * p + 1] : neg[2 * (p - 16) + 1];
        Abase = act + (size_t)i0 * Ll * Dd + half * 1024;
        if (p < 16)
            Bbase = act + (size_t)i1 * Ll * Dd + half * 1024;
        else
            Bbase = bak + (size_t)i1 * Ll * Dd + half * 1024;
        out = (half ? g_sim_g : g_sim_m) + (size_t)p * Ll * Ll;
        Ksteps = 1024 / 32;
        mode = 0;
    }
    Bbase += (size_t)colTile * Dd;

    // smem: A 128 rows x 64B (8KB), B 64 rows x 64B (4KB) + norms
    __shared__ uint4 smBuf[(128 * 64 + 64 * 64) / 16];
    __shared__ float rnAs[128];
    __shared__ float rnBs[64];
    char* smc = (char*)smBuf;
    uint32_t smemBase = (uint32_t)__cvta_generic_to_shared(smc);

    int tid  = threadIdx.x;
    int lane = tid & 31;
    int warp = tid >> 5;
    int wm = warp >> 1;
    int wn = warp & 1;

    int aRow0 = tid >> 2,            aKg0 = tid & 3;   // rows 0..63
    int aRow1 = (tid + 256) >> 2,    aKg1 = tid & 3;   // rows 64..127
    int bRow  = tid >> 2,            bKg  = tid & 3;   // B rows 0..63

    float acc[2][4][4];
#pragma unroll
    for (int i = 0; i < 2; ++i)
#pragma unroll
        for (int j = 0; j < 4; ++j)
#pragma unroll
            for (int q = 0; q < 4; ++q) acc[i][j][q] = 0.0f;

    float sqA0 = 0.0f, sqA1 = 0.0f, sqB = 0.0f;
    float4 bufA[2][2], bufB[2];

    // preload chunk 0
    {
        const float* p0 = Abase + (size_t)aRow0 * Dd + aKg0 * 8;
        bufA[0][0] = *(const float4*)(p0);
        bufA[0][1] = *(const float4*)(p0 + 4);
        const float* p1 = Abase + (size_t)aRow1 * Dd + aKg1 * 8;
        bufA[1][0] = *(const float4*)(p1);
        bufA[1][1] = *(const float4*)(p1 + 4);
        const float* pb = Bbase + (size_t)bRow * Dd + bKg * 8;
        bufB[0] = *(const float4*)(pb);
        bufB[1] = *(const float4*)(pb + 4);
    }

    int grp = lane >> 3, r8 = lane & 7;
    uint32_t aRowL = (uint32_t)(r8 + (grp & 1) * 8);
    uint32_t aColL = (uint32_t)((grp >> 1) * 8);
    uint32_t bRowL = (uint32_t)(r8 + (grp >> 1) * 8);
    uint32_t bColL = (uint32_t)((grp & 1) * 8);

    for (int kt = 0; kt < Ksteps; ++kt) {
        // STS (fp32 -> bf16) + fused sum-of-squares
        {
            const float* fa0 = (const float*)&bufA[0][0];
            const float* fa1 = (const float*)&bufA[1][0];
            const float* fbb = (const float*)&bufB[0];
#pragma unroll
            for (int q = 0; q < 8; ++q) {
                sqA0 = fmaf(fa0[q], fa0[q], sqA0);
                sqA1 = fmaf(fa1[q], fa1[q], sqA1);
                sqB  = fmaf(fbb[q], fbb[q], sqB);
            }
            uint4 v;
            v.x = pk_bf2(fa0[0], fa0[1]); v.y = pk_bf2(fa0[2], fa0[3]);
            v.z = pk_bf2(fa0[4], fa0[5]); v.w = pk_bf2(fa0[6], fa0[7]);
            *(uint4*)(smc + swz(aRow0, aKg0 * 8)) = v;
            v.x = pk_bf2(fa1[0], fa1[1]); v.y = pk_bf2(fa1[2], fa1[3]);
            v.z = pk_bf2(fa1[4], fa1[5]); v.w = pk_bf2(fa1[6], fa1[7]);
            *(uint4*)(smc + swz(aRow1, aKg1 * 8)) = v;
            v.x = pk_bf2(fbb[0], fbb[1]); v.y = pk_bf2(fbb[2], fbb[3]);
            v.z = pk_bf2(fbb[4], fbb[5]); v.w = pk_bf2(fbb[6], fbb[7]);
            *(uint4*)(smc + 8192 + swz(bRow, bKg * 8)) = v;
        }
        __syncthreads();

        if (kt + 1 < Ksteps) {
            int k0 = (kt + 1) * 32;
            const float* p0 = Abase + (size_t)aRow0 * Dd + k0 + aKg0 * 8;
            bufA[0][0] = *(const float4*)(p0);
            bufA[0][1] = *(const float4*)(p0 + 4);
            const float* p1 = Abase + (size_t)aRow1 * Dd + k0 + aKg1 * 8;
            bufA[1][0] = *(const float4*)(p1);
            bufA[1][1] = *(const float4*)(p1 + 4);
            const float* pb = Bbase + (size_t)bRow * Dd + k0 + bKg * 8;
            bufB[0] = *(const float4*)(pb);
            bufB[1] = *(const float4*)(pb + 4);
        }

#pragma unroll
        for (int ks = 0; ks < 2; ++ks) {
            int k0 = ks * 16;
            uint32_t afr[2][4];
#pragma unroll
            for (int tm = 0; tm < 2; ++tm) {
                uint32_t m0 = (uint32_t)(wm * 32 + tm * 16);
                uint32_t addrA = smemBase + swz(m0 + aRowL, (uint32_t)k0 + aColL);
                ldsm4(addrA, afr[tm][0], afr[tm][1], afr[tm][2], afr[tm][3]);
            }
            uint32_t bfr[2][4];
#pragma unroll
            for (int tb = 0; tb < 2; ++tb) {
                uint32_t n0 = (uint32_t)(wn * 32 + tb * 16);
                uint32_t addrB = smemBase + 8192u + swz(n0 + bRowL, (uint32_t)k0 + bColL);
                ldsm4(addrB, bfr[tb][0], bfr[tb][1], bfr[tb][2], bfr[tb][3]);
            }
#pragma unroll
            for (int tm = 0; tm < 2; ++tm)
#pragma unroll
                for (int tn = 0; tn < 4; ++tn) {
                    int tb = tn >> 1, wh = tn & 1;
                    mma16816(acc[tm][tn], afr[tm], bfr[tb][wh * 2], bfr[tb][wh * 2 + 1]);
                }
        }
        __syncthreads();
    }

    // reduce squares across the 4 loader lanes (adjacent lanes in warp)
    sqA0 += __shfl_xor_sync(0xffffffffu, sqA0, 1);
    sqA0 += __shfl_xor_sync(0xffffffffu, sqA0, 2);
    sqA1 += __shfl_xor_sync(0xffffffffu, sqA1, 1);
    sqA1 += __shfl_xor_sync(0xffffffffu, sqA1, 2);
    sqB  += __shfl_xor_sync(0xffffffffu, sqB, 1);
    sqB  += __shfl_xor_sync(0xffffffffu, sqB, 2);
    if ((tid & 3) == 0) {
        rnAs[aRow0] = rsqrtf(sqA0);
        rnAs[aRow1] = rsqrtf(sqA1);
        rnBs[bRow]  = rsqrtf(sqB);
    }
    __syncthreads();

    // epilogue
    int g8 = lane >> 2, tq = lane & 3;
#pragma unroll
    for (int tm = 0; tm < 2; ++tm) {
        int row0 = wm * 32 + tm * 16 + g8;
        int row1 = row0 + 8;
        float ra0 = rnAs[row0], ra1 = rnAs[row1];
#pragma unroll
        for (int tn = 0; tn < 4; ++tn) {
            int lcol = wn * 32 + tn * 8 + 2 * tq;
            int col = colTile + lcol;
            float rb0 = rnBs[lcol], rb1 = rnBs[lcol + 1];
            float v00 = acc[tm][tn][0] * ra0 * rb0;
            float v01 = acc[tm][tn][1] * ra0 * rb1;
            float v10 = acc[tm][tn][2] * ra1 * rb0;
            float v11 = acc[tm][tn][3] * ra1 * rb1;
            if (mode) {       // LCS transform
                v00 = fmaxf(0.0f, v00 - 0.8f) * 5.0f;
                v01 = fmaxf(0.0f, v01 - 0.8f) * 5.0f;
                v10 = fmaxf(0.0f, v10 - 0.8f) * 5.0f;
                v11 = fmaxf(0.0f, v11 - 0.8f) * 5.0f;
            } else {          // FSD log2x10 domain
                v00 *= FSD_SCALE; v01 *= FSD_SCALE;
                v10 *= FSD_SCALE; v11 *= FSD_SCALE;
            }
            *(float2*)(out + row0 * Ll + col) = make_float2(v00, v01);
            *(float2*)(out + row1 * Ll + col) = make_float2(v10, v11);
        }
    }
}

// ---------------------------------------------------------------------------
// DP + small losses in one kernel.
// Blocks 0..31: FSD DP, 32..63: LCS DP, 64..95: small-loss work.
// DP: smem-staged sims; single-warp skewed wavefront, strided rows
// (thread t owns rows t, t+32, t+64, t+96), 4 independent cells/step.
// ---------------------------------------------------------------------------
__device__ __forceinline__ float ex2f(float x) {
    float y; asm("ex2.approx.f32 %0, %1;" : "=f"(y) : "f"(x)); return y;
}
__device__ __forceinline__ float lg2f(float x) {
    float y; asm("lg2.approx.f32 %0, %1;" : "=f"(y) : "f"(x)); return y;
}

__global__ void k_dpall(const float* __restrict__ xi,
                        const float* __restrict__ xc,
                        const float* __restrict__ xb,
                        const float* __restrict__ vid,
                        const float* __restrict__ att,
                        const float* __restrict__ fi,
                        const float* __restrict__ fc,
                        const float* __restrict__ fb,
                        const float* __restrict__ cas) {
    extern __shared__ float dsm[];    // Ms[16384] (+ Gs[16384] for FSD)
    int b = blockIdx.x;
    int tid = threadIdx.x;

    if (b >= 64) {
        // ---------------- small-loss path (128 threads) ----------------
        __shared__ float red[128];
        int bb = b - 64;     // batch element 0..31

        float guide = 0.0f, sparse = 0.0f, si2 = 0.0f, sc2 = 0.0f, sb2 = 0.0f;
        for (int tt = tid; tt < Tt; tt += 128) {
            float cas20 = cas[((size_t)bb * Tt + tt) * (NCLS + 1) + NCLS];
            float a0 = att[((size_t)bb * Tt + tt) * 3 + 0];
            float a1 = att[((size_t)bb * Tt + tt) * 3 + 1];
            guide  += fabsf(1.0f - cas20 - a0);
            sparse += a0 + a1;
        }
        for (int k = tid; k < Dd; k += 128) {
            float v1 = fi[(size_t)bb * Dd + k];
            float v2 = fc[(size_t)bb * Dd + k];
            float v3 = fb[(size_t)bb * Dd + k];
            si2 += v1 * v1; sc2 += v2 * v2; sb2 += v3 * v3;
        }
        float vals[5] = {guide, sparse, si2, sc2, sb2};
#pragma unroll
        for (int v = 0; v < 5; ++v) {
            red[tid] = vals[v];
            __syncthreads();
            for (int s = 64; s > 0; s >>= 1) {
                if (tid < s) red[tid] += red[tid + s];
                __syncthreads();
            }
            vals[v] = red[0];
            __syncthreads();
        }
        if (tid == 0) {
            float ni = sqrtf(vals[2]);
            float nc = sqrtf(vals[3]);
            float nb = sqrtf(vals[4]);
            float f1 = fmaxf(50.0f - ni + nc, 0.0f);
            float f2 = fmaxf(50.0f - nc + nb, 0.0f);
            float feat = (f1 + f2 + nb) * (f1 + f2 + nb);

            float sv = 0.0f, s_i = 0.0f, s_c = 0.0f;
            for (int c = 0; c < NCLS; ++c) {
                float l = vid[bb * NCLS + c];
                sv  += l;
                s_i += l * logf(xi[bb * (NCLS + 1) + c] + 1e-45f);
                s_c += l * logf(xc[bb * (NCLS + 1) + c] + 1e-45f);
            }
            float inst_b = -s_i / sv;
            float cont_b = -(s_c + logf(xc[bb * (NCLS + 1) + NCLS] + 1e-45f)) / (sv + 1.0f);
            float back_b = -logf(xb[bb * (NCLS + 1) + NCLS] + 1e-45f);

            atomicAdd(&g_partial[0], inst_b + cont_b + back_b);
            atomicAdd(&g_partial[1], vals[0]);
            atomicAdd(&g_partial[2], feat);
            atomicAdd(&g_partial[3], vals[1]);
        }
        return;
    }

    // ---------------- DP path ----------------
    bool isFsd = (b < 32);
    int pair = isFsd ? b : b - 32;
    float* Ms = dsm;
    float* Gs = dsm + 16384;

    {
        const float* Mb = (isFsd ? g_sim_m : g_sim_lcs) + (size_t)pair * 16384;
        for (int idx = tid * 4; idx < 16384; idx += 512)
            *(float4*)(Ms + idx) = *(const float4*)(Mb + idx);
        if (isFsd) {
            const float* Gb = g_sim_g + (size_t)pair * 16384;
            for (int idx = tid * 4; idx < 16384; idx += 512)
                *(float4*)(Gs + idx) = *(const float4*)(Gb + idx);
        }
    }
    __syncthreads();
    if (tid >= 32) return;

    int t = tid;
    float v0 = 0.f, v1 = 0.f, v2 = 0.f, v3 = 0.f;        // left values
    float d0 = 0.f, d1 = 0.f, d2 = 0.f, d3 = 0.f;        // diag (prev ups)
    int i0 = t, i1 = t + 32, i2 = t + 64, i3 = t + 96;   // owned rows
    int b0 = i0 * 127, b1 = i1 * 127, b2 = i2 * 127, b3 = i3 * 127;

    if (isFsd) {
        for (int s = 0; s < 255; ++s) {
            float au0 = __shfl_up_sync(0xffffffffu, v0, 1);
            float au1 = __shfl_up_sync(0xffffffffu, v1, 1);
            float au2 = __shfl_up_sync(0xffffffffu, v2, 1);
            float au3 = __shfl_up_sync(0xffffffffu, v3, 1);
            float bc0 = __shfl_sync(0xffffffffu, v0, 31);
            float bc1 = __shfl_sync(0xffffffffu, v1, 31);
            float bc2 = __shfl_sync(0xffffffffu, v2, 31);
            float a0 = t ? au0 : 0.f;
            float a1 = t ? au1 : bc0;
            float a2 = t ? au2 : bc1;
            float a3 = t ? au3 : bc2;
            if ((unsigned)(s - i0) < 128u) {
                float g = Gs[b0 + s], m = Ms[b0 + s];
                float x1 = g + a0, x2 = g + v0;
                float mx = fmaxf(fmaxf(d0, x2), x1);
                float e = ex2f(d0 - mx) + ex2f(x1 - mx) + ex2f(x2 - mx);
                v0 = m + mx + lg2f(e);
            }
            if ((unsigned)(s - i1) < 128u) {
                float g = Gs[b1 + s], m = Ms[b1 + s];
                float x1 = g + a1, x2 = g + v1;
                float mx = fmaxf(fmaxf(d1, x2), x1);
                float e = ex2f(d1 - mx) + ex2f(x1 - mx) + ex2f(x2 - mx);
                v1 = m + mx + lg2f(e);
            }
            if ((unsigned)(s - i2) < 128u) {
                float g = Gs[b2 + s], m = Ms[b2 + s];
                float x1 = g + a2, x2 = g + v2;
                float mx = fmaxf(fmaxf(d2, x2), x1);
                float e = ex2f(d2 - mx) + ex2f(x1 - mx) + ex2f(x2 - mx);
                v2 = m + mx + lg2f(e);
            }
            if ((unsigned)(s - i3) < 128u) {
                float g = Gs[b3 + s], m = Ms[b3 + s];
                float x1 = g + a3, x2 = g + v3;
                float mx = fmaxf(fmaxf(d3, x2), x1);
                float e = ex2f(d3 - mx) + ex2f(x1 - mx) + ex2f(x2 - mx);
                v3 = m + mx + lg2f(e);
            }
            d0 = a0; d1 = a1; d2 = a2; d3 = a3;
        }
        if (t == 31)
            atomicAdd(&g_partial[pair < 16 ? 6 : 7], v3 * FSD_UNSCALE);
    } else {
        for (int s = 0; s < 255; ++s) {
            float au0 = __shfl_up_sync(0xffffffffu, v0, 1);
            float au1 = __shfl_up_sync(0xffffffffu, v1, 1);
            float au2 = __shfl_up_sync(0xffffffffu, v2, 1);
            float au3 = __shfl_up_sync(0xffffffffu, v3, 1);
            float bc0 = __shfl_sync(0xffffffffu, v0, 31);
            float bc1 = __shfl_sync(0xffffffffu, v1, 31);
            float bc2 = __shfl_sync(0xffffffffu, v2, 31);
            float a0 = t ? au0 : 0.f;
            float a1 = t ? au1 : bc0;
            float a2 = t ? au2 : bc1;
            float a3 = t ? au3 : bc2;
            if ((unsigned)(s - i0) < 128u) {
                float sv = Ms[b0 + s];
                v0 = (sv > 0.5f) ? d0 + sv : fmaxf(a0, v0);
            }
            if ((unsigned)(s - i1) < 128u) {
                float sv = Ms[b1 + s];
                v1 = (sv > 0.5f) ? d1 + sv : fmaxf(a1, v1);
            }
            if ((unsigned)(s - i2) < 128u) {
                float sv = Ms[b2 + s];
                v2 = (sv > 0.5f) ? d2 + sv : fmaxf(a2, v2);
            }
            if ((unsigned)(s - i3) < 128u) {
                float sv = Ms[b3 + s];
                v3 = (sv > 0.5f) ? d3 + sv : fmaxf(a3, v3);
            }
            d0 = a0; d1 = a1; d2 = a2; d3 = a3;
        }
        if (t == 31)
            atomicAdd(&g_partial[pair < 16 ? 4 : 5], v3);
    }
}

__global__ void k_combine(float* out) {
    float cls    = g_partial[0] / 32.0f;
    float guide  = g_partial[1] / 32.0f;
    float feat   = g_partial[2] / 32.0f;
    float sparse = g_partial[3] / 64.0f;
    float acm = cls + 1.0f * guide + 5e-5f * feat + 2e-4f * sparse;
    float lcs_loss = (g_partial[5] - g_partial[4]) / 16.0f;
    float fsd_loss = (g_partial[7] - g_partial[6]) / 16.0f;
    out[0] = acm + 0.1f * lcs_loss + 0.1f * fsd_loss;
}

// ---------------------------------------------------------------------------
// Launch
// ---------------------------------------------------------------------------
extern "C" void kernel_launch(void* const* d_in, const int* in_sizes, int n_in,
                              void* d_out, int out_size) {
    const float* xi  = (const float*)d_in[0];
    const float* xc  = (const float*)d_in[1];
    const float* xb  = (const float*)d_in[2];
    const float* vid = (const float*)d_in[3];
    const float* att = (const float*)d_in[4];
    const float* fi  = (const float*)d_in[5];
    const float* fc  = (const float*)d_in[6];
    const float* fb  = (const float*)d_in[7];
    const float* cas = (const float*)d_in[8];
    const float* lcs = (const float*)d_in[9];
    const float* act = (const float*)d_in[10];
    const float* bak = (const float*)d_in[11];
    const int*   pos = (const int*)d_in[12];
    const int*   neg = (const int*)d_in[13];
    float* out = (float*)d_out;

    const int dp_smem = 2 * 16384 * (int)sizeof(float);   // 128 KB
    cudaFuncSetAttribute(k_dpall, cudaFuncAttributeMaxDynamicSharedMemorySize, dp_smem);

    k_init<<<1, 32>>>();
    k_gemm<<<192, 256>>>(lcs, act, bak, pos, neg);
    k_dpall<<<96, 128, dp_smem>>>(xi, xc, xb, vid, att, fi, fc, fb, cas);
    k_combine<<<1, 1>>>(out);
}

// round 6
// speedup vs baseline: 2.3563x; 1.1950x over previous
#include <cuda_runtime.h>
#include <cuda_bf16.h>
#include <stdint.h>
#include <math.h>

#define Bv    32
#define NCLS  20
#define Tt    2048
#define Dd    2048
#define Ll    128

// FSD scale: 10 * log2(e)  (gamma=0.1 -> log2 x10 domain)
#define FSD_SCALE 14.426950408889634f
#define FSD_UNSCALE 0.06931471805599453f

// ---------------------------------------------------------------------------
// Device scratch
// ---------------------------------------------------------------------------
__device__ float g_sim_lcs[32 * Ll * Ll];   // final transformed LCS s
__device__ float g_sim_m[32 * Ll * Ll];     // FSD m (x FSD_SCALE)
__device__ float g_sim_g[32 * Ll * Ll];     // FSD g (x FSD_SCALE)
__device__ float g_dotL0[32 * Ll * Ll];     // LCS raw dots, K half 0
__device__ float g_dotL1[32 * Ll * Ll];     // LCS raw dots, K half 1
__device__ float g_nAL[2][32][128];         // LCS A sq partials [kh][pair][row]
__device__ float g_nBL[2][32][128];         // LCS B sq partials [kh][pair][col]
// 0 cls, 1 guide, 2 feat, 3 sparse, 4 posLCS, 5 negLCS, 6 act_act, 7 act_bak
__device__ float g_partial[8];
__device__ unsigned int g_done = 0;

// ---------------------------------------------------------------------------
// GEMM helpers
// ---------------------------------------------------------------------------
__device__ __forceinline__ uint32_t swz(uint32_t row, uint32_t col) {
    return row * 64u + ((((col >> 3) ^ ((row >> 1) & 3u)) << 4)) + ((col & 7u) << 1);
}
__device__ __forceinline__ uint32_t pk_bf2(float lo, float hi) {
    __nv_bfloat162 h = __floats2bfloat162_rn(lo, hi);
    return *(uint32_t*)&h;
}
__device__ __forceinline__ void ldsm4(uint32_t addr, uint32_t& r0, uint32_t& r1,
                                      uint32_t& r2, uint32_t& r3) {
    asm volatile("ldmatrix.sync.aligned.m8n8.x4.shared.b16 {%0,%1,%2,%3}, [%4];"
                 : "=r"(r0), "=r"(r1), "=r"(r2), "=r"(r3) : "r"(addr));
}
__device__ __forceinline__ void mma16816(float* c, const uint32_t* a,
                                         uint32_t b0, uint32_t b1) {
    asm volatile("mma.sync.aligned.m16n8k16.row.col.f32.bf16.bf16.f32 "
                 "{%0,%1,%2,%3}, {%4,%5,%6,%7}, {%8,%9}, {%0,%1,%2,%3};"
                 : "+f"(c[0]), "+f"(c[1]), "+f"(c[2]), "+f"(c[3])
                 : "r"(a[0]), "r"(a[1]), "r"(a[2]), "r"(a[3]), "r"(b0), "r"(b1));
}

// ---------------------------------------------------------------------------
// bf16 tensor-core GEMM, balanced blocks (all Ksteps = 32), double-buffered.
// blk [0,128):   FSD: f = blk>>1, colTile=(blk&1)*64. Final write (mode 0).
// blk [128,256): LCS: q=blk-128, p=q>>2, colTile=((q>>1)&1)*64, kh=q&1.
//                Raw dot write + sq partials (mode 1).
// ---------------------------------------------------------------------------
#define STAGE_BYTES 12288
#define KSTEPS 32

__global__ __launch_bounds__(256, 2)
void k_gemm(const float* __restrict__ lcs,
            const float* __restrict__ act,
            const float* __restrict__ bak,
            const int* __restrict__ pos,
            const int* __restrict__ neg) {
    int blk = blockIdx.x;
    const float *Abase, *Bbase;
    float* out;
    int mode;          // 0 = FSD final, 1 = LCS raw split-K
    int colTile, p_idx, kh = 0;

    if (blk < 128) {
        int f = blk >> 1;
        colTile = (blk & 1) * 64;
        int p = f >> 1;
        int half = f & 1;
        p_idx = p;
        int i0 = (p < 16) ? pos[2 * p]     : neg[2 * (p - 16)];
        int i1 = (p < 16) ? pos[2 * p + 1] : neg[2 * (p - 16) + 1];
        Abase = act + (size_t)i0 * Ll * Dd + half * 1024;
        if (p < 16)
            Bbase = act + (size_t)i1 * Ll * Dd + half * 1024;
        else
            Bbase = bak + (size_t)i1 * Ll * Dd + half * 1024;
        out = (half ? g_sim_g : g_sim_m) + (size_t)p * Ll * Ll;
        mode = 0;
    } else {
        int q = blk - 128;
        int p = q >> 2;
        colTile = ((q >> 1) & 1) * 64;
        kh = q & 1;
        p_idx = p;
        int i0 = (p < 16) ? pos[2 * p]     : neg[2 * (p - 16)];
        int i1 = (p < 16) ? pos[2 * p + 1] : neg[2 * (p - 16) + 1];
        Abase = lcs + (size_t)i0 * Ll * Dd + kh * 1024;
        Bbase = lcs + (size_t)i1 * Ll * Dd + kh * 1024;
        out = (kh ? g_dotL1 : g_dotL0) + (size_t)p * Ll * Ll;
        mode = 1;
    }
    Bbase += (size_t)colTile * Dd;

    // double-buffered smem: 2 stages x (A 8KB + B 4KB)
    __shared__ uint4 smBuf[2 * STAGE_BYTES / 16];
    __shared__ float rnAs[128];
    __shared__ float rnBs[64];
    char* smc = (char*)smBuf;
    uint32_t smemBase = (uint32_t)__cvta_generic_to_shared(smc);

    int tid  = threadIdx.x;
    int lane = tid & 31;
    int warp = tid >> 5;
    int wm = warp >> 1;
    int wn = warp & 1;

    int aRow0 = tid >> 2,            aKg0 = tid & 3;
    int aRow1 = (tid + 256) >> 2,    aKg1 = tid & 3;
    int bRow  = tid >> 2,            bKg  = tid & 3;

    float acc[2][4][4];
#pragma unroll
    for (int i = 0; i < 2; ++i)
#pragma unroll
        for (int j = 0; j < 4; ++j)
#pragma unroll
            for (int q2 = 0; q2 < 4; ++q2) acc[i][j][q2] = 0.0f;

    float sqA0 = 0.0f, sqA1 = 0.0f, sqB = 0.0f;
    float4 bufA[2][2], bufB[2];

    const float* pA0 = Abase + (size_t)aRow0 * Dd + aKg0 * 8;
    const float* pA1 = Abase + (size_t)aRow1 * Dd + aKg1 * 8;
    const float* pB  = Bbase + (size_t)bRow  * Dd + bKg  * 8;

    // preload + stage 0 fill
    bufA[0][0] = *(const float4*)(pA0);
    bufA[0][1] = *(const float4*)(pA0 + 4);
    bufA[1][0] = *(const float4*)(pA1);
    bufA[1][1] = *(const float4*)(pA1 + 4);
    bufB[0]    = *(const float4*)(pB);
    bufB[1]    = *(const float4*)(pB + 4);

    {
        const float* fa0 = (const float*)&bufA[0][0];
        const float* fa1 = (const float*)&bufA[1][0];
        const float* fbb = (const float*)&bufB[0];
#pragma unroll
        for (int q2 = 0; q2 < 8; ++q2) {
            sqA0 = fmaf(fa0[q2], fa0[q2], sqA0);
            sqA1 = fmaf(fa1[q2], fa1[q2], sqA1);
            sqB  = fmaf(fbb[q2], fbb[q2], sqB);
        }
        uint4 v;
        v.x = pk_bf2(fa0[0], fa0[1]); v.y = pk_bf2(fa0[2], fa0[3]);
        v.z = pk_bf2(fa0[4], fa0[5]); v.w = pk_bf2(fa0[6], fa0[7]);
        *(uint4*)(smc + swz(aRow0, aKg0 * 8)) = v;
        v.x = pk_bf2(fa1[0], fa1[1]); v.y = pk_bf2(fa1[2], fa1[3]);
        v.z = pk_bf2(fa1[4], fa1[5]); v.w = pk_bf2(fa1[6], fa1[7]);
        *(uint4*)(smc + swz(aRow1, aKg1 * 8)) = v;
        v.x = pk_bf2(fbb[0], fbb[1]); v.y = pk_bf2(fbb[2], fbb[3]);
        v.z = pk_bf2(fbb[4], fbb[5]); v.w = pk_bf2(fbb[6], fbb[7]);
        *(uint4*)(smc + 8192 + swz(bRow, bKg * 8)) = v;
    }
    __syncthreads();

    int grp = lane >> 3, r8 = lane & 7;
    uint32_t aRowL = (uint32_t)(r8 + (grp & 1) * 8);
    uint32_t aColL = (uint32_t)((grp >> 1) * 8);
    uint32_t bRowL = (uint32_t)(r8 + (grp >> 1) * 8);
    uint32_t bColL = (uint32_t)((grp & 1) * 8);

    for (int kt = 0; kt < KSTEPS; ++kt) {
        // prefetch next chunk
        if (kt + 1 < KSTEPS) {
            int k0 = (kt + 1) * 32;
            bufA[0][0] = *(const float4*)(pA0 + k0);
            bufA[0][1] = *(const float4*)(pA0 + k0 + 4);
            bufA[1][0] = *(const float4*)(pA1 + k0);
            bufA[1][1] = *(const float4*)(pA1 + k0 + 4);
            bufB[0]    = *(const float4*)(pB + k0);
            bufB[1]    = *(const float4*)(pB + k0 + 4);
        }

        // compute current stage
        uint32_t stBase = smemBase + (uint32_t)(kt & 1) * STAGE_BYTES;
#pragma unroll
        for (int ks = 0; ks < 2; ++ks) {
            int k0 = ks * 16;
            uint32_t afr[2][4];
#pragma unroll
            for (int tm = 0; tm < 2; ++tm) {
                uint32_t m0 = (uint32_t)(wm * 32 + tm * 16);
                uint32_t addrA = stBase + swz(m0 + aRowL, (uint32_t)k0 + aColL);
                ldsm4(addrA, afr[tm][0], afr[tm][1], afr[tm][2], afr[tm][3]);
            }
            uint32_t bfr[2][4];
#pragma unroll
            for (int tb = 0; tb < 2; ++tb) {
                uint32_t n0 = (uint32_t)(wn * 32 + tb * 16);
                uint32_t addrB = stBase + 8192u + swz(n0 + bRowL, (uint32_t)k0 + bColL);
                ldsm4(addrB, bfr[tb][0], bfr[tb][1], bfr[tb][2], bfr[tb][3]);
            }
#pragma unroll
            for (int tm = 0; tm < 2; ++tm)
#pragma unroll
                for (int tn = 0; tn < 4; ++tn) {
                    int tb = tn >> 1, wh = tn & 1;
                    mma16816(acc[tm][tn], afr[tm], bfr[tb][wh * 2], bfr[tb][wh * 2 + 1]);
                }
        }

        // fill next stage
        if (kt + 1 < KSTEPS) {
            char* nst = smc + ((kt + 1) & 1) * STAGE_BYTES;
            const float* fa0 = (const float*)&bufA[0][0];
            const float* fa1 = (const float*)&bufA[1][0];
            const float* fbb = (const float*)&bufB[0];
#pragma unroll
            for (int q2 = 0; q2 < 8; ++q2) {
                sqA0 = fmaf(fa0[q2], fa0[q2], sqA0);
                sqA1 = fmaf(fa1[q2], fa1[q2], sqA1);
                sqB  = fmaf(fbb[q2], fbb[q2], sqB);
            }
            uint4 v;
            v.x = pk_bf2(fa0[0], fa0[1]); v.y = pk_bf2(fa0[2], fa0[3]);
            v.z = pk_bf2(fa0[4], fa0[5]); v.w = pk_bf2(fa0[6], fa0[7]);
            *(uint4*)(nst + swz(aRow0, aKg0 * 8)) = v;
            v.x = pk_bf2(fa1[0], fa1[1]); v.y = pk_bf2(fa1[2], fa1[3]);
            v.z = pk_bf2(fa1[4], fa1[5]); v.w = pk_bf2(fa1[6], fa1[7]);
            *(uint4*)(nst + swz(aRow1, aKg1 * 8)) = v;
            v.x = pk_bf2(fbb[0], fbb[1]); v.y = pk_bf2(fbb[2], fbb[3]);
            v.z = pk_bf2(fbb[4], fbb[5]); v.w = pk_bf2(fbb[6], fbb[7]);
            *(uint4*)(nst + 8192 + swz(bRow, bKg * 8)) = v;
        }
        __syncthreads();
    }

    // reduce sq partials across the 4 loader lanes
    sqA0 += __shfl_xor_sync(0xffffffffu, sqA0, 1);
    sqA0 += __shfl_xor_sync(0xffffffffu, sqA0, 2);
    sqA1 += __shfl_xor_sync(0xffffffffu, sqA1, 1);
    sqA1 += __shfl_xor_sync(0xffffffffu, sqA1, 2);
    sqB  += __shfl_xor_sync(0xffffffffu, sqB, 1);
    sqB  += __shfl_xor_sync(0xffffffffu, sqB, 2);

    if (mode == 1) {
        // LCS split-K: store sq partials + raw dots
        if ((tid & 3) == 0) {
            g_nAL[kh][p_idx][aRow0] = sqA0;
            g_nAL[kh][p_idx][aRow1] = sqA1;
            g_nBL[kh][p_idx][colTile + bRow] = sqB;
        }
        int g8 = lane >> 2, tq = lane & 3;
#pragma unroll
        for (int tm = 0; tm < 2; ++tm) {
            int row0 = wm * 32 + tm * 16 + g8;
            int row1 = row0 + 8;
#pragma unroll
            for (int tn = 0; tn < 4; ++tn) {
                int col = colTile + wn * 32 + tn * 8 + 2 * tq;
                *(float2*)(out + row0 * Ll + col) =
                    make_float2(acc[tm][tn][0], acc[tm][tn][1]);
                *(float2*)(out + row1 * Ll + col) =
                    make_float2(acc[tm][tn][2], acc[tm][tn][3]);
            }
        }
        return;
    }

    // FSD: finalize with norms in smem
    if ((tid & 3) == 0) {
        rnAs[aRow0] = rsqrtf(sqA0);
        rnAs[aRow1] = rsqrtf(sqA1);
        rnBs[bRow]  = rsqrtf(sqB);
    }
    __syncthreads();

    int g8 = lane >> 2, tq = lane & 3;
#pragma unroll
    for (int tm = 0; tm < 2; ++tm) {
        int row0 = wm * 32 + tm * 16 + g8;
        int row1 = row0 + 8;
        float ra0 = rnAs[row0], ra1 = rnAs[row1];
#pragma unroll
        for (int tn = 0; tn < 4; ++tn) {
            int lcol = wn * 32 + tn * 8 + 2 * tq;
            int col = colTile + lcol;
            float rb0 = rnBs[lcol], rb1 = rnBs[lcol + 1];
            float v00 = acc[tm][tn][0] * ra0 * rb0 * FSD_SCALE;
            float v01 = acc[tm][tn][1] * ra0 * rb1 * FSD_SCALE;
            float v10 = acc[tm][tn][2] * ra1 * rb0 * FSD_SCALE;
            float v11 = acc[tm][tn][3] * ra1 * rb1 * FSD_SCALE;
            *(float2*)(out + row0 * Ll + col) = make_float2(v00, v01);
            *(float2*)(out + row1 * Ll + col) = make_float2(v10, v11);
        }
    }
}

// ---------------------------------------------------------------------------
// LCS epilogue: combine K halves, normalize, transform. Also zero partials.
// ---------------------------------------------------------------------------
__global__ void k_epi() {
    __shared__ float rA[128], rB[128];
    int p = blockIdx.x, tid = threadIdx.x;
    if (tid < 128) {
        rA[tid] = rsqrtf(g_nAL[0][p][tid] + g_nAL[1][p][tid]);
    } else {
        int c = tid - 128;
        rB[c] = rsqrtf(g_nBL[0][p][c] + g_nBL[1][p][c]);
    }
    if (p == 0 && tid < 8) g_partial[tid] = 0.0f;
    __syncthreads();

    const float* d0 = g_dotL0 + (size_t)p * 16384;
    const float* d1 = g_dotL1 + (size_t)p * 16384;
    float* o = g_sim_lcs + (size_t)p * 16384;
    for (int e = tid * 4; e < 16384; e += 1024) {
        float4 a = *(const float4*)(d0 + e);
        float4 b = *(const float4*)(d1 + e);
        int row = e >> 7, col = e & 127;
        float ra = rA[row];
        float4 r;
        r.x = fmaxf(0.0f, (a.x + b.x) * ra * rB[col + 0] - 0.8f) * 5.0f;
        r.y = fmaxf(0.0f, (a.y + b.y) * ra * rB[col + 1] - 0.8f) * 5.0f;
        r.z = fmaxf(0.0f, (a.z + b.z) * ra * rB[col + 2] - 0.8f) * 5.0f;
        r.w = fmaxf(0.0f, (a.w + b.w) * ra * rB[col + 3] - 0.8f) * 5.0f;
        *(float4*)(o + e) = r;
    }
}

// ---------------------------------------------------------------------------
// DP + small losses + final combine (last block).
// ---------------------------------------------------------------------------
__device__ __forceinline__ float ex2f(float x) {
    float y; asm("ex2.approx.f32 %0, %1;" : "=f"(y) : "f"(x)); return y;
}
__device__ __forceinline__ float lg2f(float x) {
    float y; asm("lg2.approx.f32 %0, %1;" : "=f"(y) : "f"(x)); return y;
}

__device__ __forceinline__ void block_done(float* out) {
    __threadfence();
    unsigned v = atomicAdd(&g_done, 1u);
    if (v == 95u) {
        volatile float* gp = g_partial;
        float cls    = gp[0] / 32.0f;
        float guide  = gp[1] / 32.0f;
        float feat   = gp[2] / 32.0f;
        float sparse = gp[3] / 64.0f;
        float acm = cls + guide + 5e-5f * feat + 2e-4f * sparse;
        float lcs_loss = (gp[5] - gp[4]) / 16.0f;
        float fsd_loss = (gp[7] - gp[6]) / 16.0f;
        out[0] = acm + 0.1f * lcs_loss + 0.1f * fsd_loss;
        g_done = 0;
    }
}

__global__ void k_dpall(const float* __restrict__ xi,
                        const float* __restrict__ xc,
                        const float* __restrict__ xb,
                        const float* __restrict__ vid,
                        const float* __restrict__ att,
                        const float* __restrict__ fi,
                        const float* __restrict__ fc,
                        const float* __restrict__ fb,
                        const float* __restrict__ cas,
                        float* __restrict__ outp) {
    extern __shared__ float dsm[];
    int b = blockIdx.x;
    int tid = threadIdx.x;

    if (b >= 64) {
        __shared__ float red[128];
        int bb = b - 64;
        float guide = 0.0f, sparse = 0.0f, si2 = 0.0f, sc2 = 0.0f, sb2 = 0.0f;
        for (int tt = tid; tt < Tt; tt += 128) {
            float cas20 = cas[((size_t)bb * Tt + tt) * (NCLS + 1) + NCLS];
            float a0 = att[((size_t)bb * Tt + tt) * 3 + 0];
            float a1 = att[((size_t)bb * Tt + tt) * 3 + 1];
            guide  += fabsf(1.0f - cas20 - a0);
            sparse += a0 + a1;
        }
        for (int k = tid; k < Dd; k += 128) {
            float v1 = fi[(size_t)bb * Dd + k];
            float v2 = fc[(size_t)bb * Dd + k];
            float v3 = fb[(size_t)bb * Dd + k];
            si2 += v1 * v1; sc2 += v2 * v2; sb2 += v3 * v3;
        }
        float vals[5] = {guide, sparse, si2, sc2, sb2};
#pragma unroll
        for (int v = 0; v < 5; ++v) {
            red[tid] = vals[v];
            __syncthreads();
            for (int s = 64; s > 0; s >>= 1) {
                if (tid < s) red[tid] += red[tid + s];
                __syncthreads();
            }
            vals[v] = red[0];
            __syncthreads();
        }
        if (tid == 0) {
            float ni = sqrtf(vals[2]);
            float nc = sqrtf(vals[3]);
            float nb = sqrtf(vals[4]);
            float f1 = fmaxf(50.0f - ni + nc, 0.0f);
            float f2 = fmaxf(50.0f - nc + nb, 0.0f);
            float feat = (f1 + f2 + nb) * (f1 + f2 + nb);

            float sv = 0.0f, s_i = 0.0f, s_c = 0.0f;
            for (int c = 0; c < NCLS; ++c) {
                float l = vid[bb * NCLS + c];
                sv  += l;
                s_i += l * logf(xi[bb * (NCLS + 1) + c] + 1e-45f);
                s_c += l * logf(xc[bb * (NCLS + 1) + c] + 1e-45f);
            }
            float inst_b = -s_i / sv;
            float cont_b = -(s_c + logf(xc[bb * (NCLS + 1) + NCLS] + 1e-45f)) / (sv + 1.0f);
            float back_b = -logf(xb[bb * (NCLS + 1) + NCLS] + 1e-45f);

            atomicAdd(&g_partial[0], inst_b + cont_b + back_b);
            atomicAdd(&g_partial[1], vals[0]);
            atomicAdd(&g_partial[2], feat);
            atomicAdd(&g_partial[3], vals[1]);
            block_done(outp);
        }
        return;
    }

    bool isFsd = (b < 32);
    int pair = isFsd ? b : b - 32;
    float* Ms = dsm;
    float* Gs = dsm + 16384;

    {
        const float* Mb = (isFsd ? g_sim_m : g_sim_lcs) + (size_t)pair * 16384;
        for (int idx = tid * 4; idx < 16384; idx += 512)
            *(float4*)(Ms + idx) = *(const float4*)(Mb + idx);
        if (isFsd) {
            const float* Gb = g_sim_g + (size_t)pair * 16384;
            for (int idx = tid * 4; idx < 16384; idx += 512)
                *(float4*)(Gs + idx) = *(const float4*)(Gb + idx);
        }
    }
    __syncthreads();
    if (tid >= 32) return;

    int t = tid;
    float v0 = 0.f, v1 = 0.f, v2 = 0.f, v3 = 0.f;
    float d0 = 0.f, d1 = 0.f, d2 = 0.f, d3 = 0.f;
    int i0 = t, i1 = t + 32, i2 = t + 64, i3 = t + 96;
    int b0 = i0 * 127, b1 = i1 * 127, b2 = i2 * 127, b3 = i3 * 127;

    if (isFsd) {
        for (int s = 0; s < 255; ++s) {
            float au0 = __shfl_up_sync(0xffffffffu, v0, 1);
            float au1 = __shfl_up_sync(0xffffffffu, v1, 1);
            float au2 = __shfl_up_sync(0xffffffffu, v2, 1);
            float au3 = __shfl_up_sync(0xffffffffu, v3, 1);
            float bc0 = __shfl_sync(0xffffffffu, v0, 31);
            float bc1 = __shfl_sync(0xffffffffu, v1, 31);
            float bc2 = __shfl_sync(0xffffffffu, v2, 31);
            float a0 = t ? au0 : 0.f;
            float a1 = t ? au1 : bc0;
            float a2 = t ? au2 : bc1;
            float a3 = t ? au3 : bc2;
            if ((unsigned)(s - i0) < 128u) {
                float g = Gs[b0 + s], m = Ms[b0 + s];
                float x1 = g + a0, x2 = g + v0;
                float mx = fmaxf(fmaxf(d0, x2), x1);
                float e = ex2f(d0 - mx) + ex2f(x1 - mx) + ex2f(x2 - mx);
                v0 = m + mx + lg2f(e);
            }
            if ((unsigned)(s - i1) < 128u) {
                float g = Gs[b1 + s], m = Ms[b1 + s];
                float x1 = g + a1, x2 = g + v1;
                float mx = fmaxf(fmaxf(d1, x2), x1);
                float e = ex2f(d1 - mx) + ex2f(x1 - mx) + ex2f(x2 - mx);
                v1 = m + mx + lg2f(e);
            }
            if ((unsigned)(s - i2) < 128u) {
                float g = Gs[b2 + s], m = Ms[b2 + s];
                float x1 = g + a2, x2 = g + v2;
                float mx = fmaxf(fmaxf(d2, x2), x1);
                float e = ex2f(d2 - mx) + ex2f(x1 - mx) + ex2f(x2 - mx);
                v2 = m + mx + lg2f(e);
            }
            if ((unsigned)(s - i3) < 128u) {
                float g = Gs[b3 + s], m = Ms[b3 + s];
                float x1 = g + a3, x2 = g + v3;
                float mx = fmaxf(fmaxf(d3, x2), x1);
                float e = ex2f(d3 - mx) + ex2f(x1 - mx) + ex2f(x2 - mx);
                v3 = m + mx + lg2f(e);
            }
            d0 = a0; d1 = a1; d2 = a2; d3 = a3;
        }
        if (t == 31) {
            atomicAdd(&g_partial[pair < 16 ? 6 : 7], v3 * FSD_UNSCALE);
            block_done(outp);
        }
    } else {
        for (int s = 0; s < 255; ++s) {
            float au0 = __shfl_up_sync(0xffffffffu, v0, 1);
            float au1 = __shfl_up_sync(0xffffffffu, v1, 1);
            float au2 = __shfl_up_sync(0xffffffffu, v2, 1);
            float au3 = __shfl_up_sync(0xffffffffu, v3, 1);
            float bc0 = __shfl_sync(0xffffffffu, v0, 31);
            float bc1 = __shfl_sync(0xffffffffu, v1, 31);
            float bc2 = __shfl_sync(0xffffffffu, v2, 31);
            float a0 = t ? au0 : 0.f;
            float a1 = t ? au1 : bc0;
            float a2 = t ? au2 : bc1;
            float a3 = t ? au3 : bc2;
            if ((unsigned)(s - i0) < 128u) {
                float sv = Ms[b0 + s];
                v0 = (sv > 0.5f) ? d0 + sv : fmaxf(a0, v0);
            }
            if ((unsigned)(s - i1) < 128u) {
                float sv = Ms[b1 + s];
                v1 = (sv > 0.5f) ? d1 + sv : fmaxf(a1, v1);
            }
            if ((unsigned)(s - i2) < 128u) {
                float sv = Ms[b2 + s];
                v2 = (sv > 0.5f) ? d2 + sv : fmaxf(a2, v2);
            }
            if ((unsigned)(s - i3) < 128u) {
                float sv = Ms[b3 + s];
                v3 = (sv > 0.5f) ? d3 + sv : fmaxf(a3, v3);
            }
            d0 = a0; d1 = a1; d2 = a2; d3 = a3;
        }
        if (t == 31) {
            atomicAdd(&g_partial[pair < 16 ? 4 : 5], v3);
            block_done(outp);
        }
    }
}

// ---------------------------------------------------------------------------
// Launch
// ---------------------------------------------------------------------------
extern "C" void kernel_launch(void* const* d_in, const int* in_sizes, int n_in,
                              void* d_out, int out_size) {
    const float* xi  = (const float*)d_in[0];
    const float* xc  = (const float*)d_in[1];
    const float* xb  = (const float*)d_in[2];
    const float* vid = (const float*)d_in[3];
    const float* att = (const float*)d_in[4];
    const float* fi  = (const float*)d_in[5];
    const float* fc  = (const float*)d_in[6];
    const float* fb  = (const float*)d_in[7];
    const float* cas = (const float*)d_in[8];
    const float* lcs = (const float*)d_in[9];
    const float* act = (const float*)d_in[10];
    const float* bak = (const float*)d_in[11];
    const int*   pos = (const int*)d_in[12];
    const int*   neg = (const int*)d_in[13];
    float* out = (float*)d_out;

    const int dp_smem = 2 * 16384 * (int)sizeof(float);   // 128 KB
    cudaFuncSetAttribute(k_dpall, cudaFuncAttributeMaxDynamicSharedMemorySize, dp_smem);

    k_gemm<<<256, 256>>>(lcs, act, bak, pos, neg);
    k_epi<<<32, 256>>>();
    k_dpall<<<96, 128, dp_smem>>>(xi, xc, xb, vid, att, fi, fc, fb, cas, out);
}

// round 7
// speedup vs baseline: 3.6649x; 1.5554x over previous
#include <cuda_runtime.h>
#include <cuda_bf16.h>
#include <stdint.h>
#include <math.h>

#define Bv    32
#define NCLS  20
#define Tt    2048
#define Dd    2048
#define Ll    128

// FSD scale: 10 * log2(e)  (gamma=0.1 -> log2 x10 domain)
#define FSD_SCALE 14.426950408889634f
#define FSD_UNSCALE 0.06931471805599453f

// ---------------------------------------------------------------------------
// Device scratch
// ---------------------------------------------------------------------------
__device__ float g_sim_m[32 * Ll * Ll];     // FSD m (x FSD_SCALE)
__device__ float g_sim_g[32 * Ll * Ll];     // FSD g (x FSD_SCALE)
__device__ float g_dotL0[32 * Ll * Ll];     // LCS raw dots, K half 0
__device__ float g_dotL1[32 * Ll * Ll];     // LCS raw dots, K half 1
__device__ float g_nAL[2][32][128];         // LCS A sq partials [kh][pair][row]
__device__ float g_nBL[2][32][128];         // LCS B sq partials [kh][pair][col]
// 0 cls, 1 guide, 2 feat, 3 sparse, 4 posLCS, 5 negLCS, 6 act_act, 7 act_bak
__device__ float g_partial[8];
__device__ unsigned int g_done = 0;

// ---------------------------------------------------------------------------
// GEMM helpers
// ---------------------------------------------------------------------------
__device__ __forceinline__ uint32_t swz(uint32_t row, uint32_t col) {
    return row * 64u + ((((col >> 3) ^ ((row >> 1) & 3u)) << 4)) + ((col & 7u) << 1);
}
__device__ __forceinline__ uint32_t pk_bf2(float lo, float hi) {
    __nv_bfloat162 h = __floats2bfloat162_rn(lo, hi);
    return *(uint32_t*)&h;
}
__device__ __forceinline__ void ldsm4(uint32_t addr, uint32_t& r0, uint32_t& r1,
                                      uint32_t& r2, uint32_t& r3) {
    asm volatile("ldmatrix.sync.aligned.m8n8.x4.shared.b16 {%0,%1,%2,%3}, [%4];"
                 : "=r"(r0), "=r"(r1), "=r"(r2), "=r"(r3) : "r"(addr));
}
__device__ __forceinline__ void mma16816(float* c, const uint32_t* a,
                                         uint32_t b0, uint32_t b1) {
    asm volatile("mma.sync.aligned.m16n8k16.row.col.f32.bf16.bf16.f32 "
                 "{%0,%1,%2,%3}, {%4,%5,%6,%7}, {%8,%9}, {%0,%1,%2,%3};"
                 : "+f"(c[0]), "+f"(c[1]), "+f"(c[2]), "+f"(c[3])
                 : "r"(a[0]), "r"(a[1]), "r"(a[2]), "r"(a[3]), "r"(b0), "r"(b1));
}

#define STAGE_BYTES 12288
#define KSTEPS 32

// ---------------------------------------------------------------------------
// bf16 tensor-core GEMM, 256 balanced blocks (all Ksteps = 32), double buffered.
// blk [0,128):   FSD final (mode 0).  blk [128,256): LCS split-K raw (mode 1).
// ---------------------------------------------------------------------------
__global__ __launch_bounds__(256, 2)
void k_gemm(const float* __restrict__ lcs,
            const float* __restrict__ act,
            const float* __restrict__ bak,
            const int* __restrict__ pos,
            const int* __restrict__ neg) {
    int blk = blockIdx.x;
    int tid  = threadIdx.x;
    if (blk == 0 && tid < 8) g_partial[tid] = 0.0f;

    const float *Abase, *Bbase;
    float* out;
    int mode, colTile, p_idx, kh = 0;

    if (blk < 128) {
        int f = blk >> 1;
        colTile = (blk & 1) * 64;
        int p = f >> 1;
        int half = f & 1;
        p_idx = p;
        int i0 = (p < 16) ? pos[2 * p]     : neg[2 * (p - 16)];
        int i1 = (p < 16) ? pos[2 * p + 1] : neg[2 * (p - 16) + 1];
        Abase = act + (size_t)i0 * Ll * Dd + half * 1024;
        if (p < 16)
            Bbase = act + (size_t)i1 * Ll * Dd + half * 1024;
        else
            Bbase = bak + (size_t)i1 * Ll * Dd + half * 1024;
        out = (half ? g_sim_g : g_sim_m) + (size_t)p * Ll * Ll;
        mode = 0;
    } else {
        int q = blk - 128;
        int p = q >> 2;
        colTile = ((q >> 1) & 1) * 64;
        kh = q & 1;
        p_idx = p;
        int i0 = (p < 16) ? pos[2 * p]     : neg[2 * (p - 16)];
        int i1 = (p < 16) ? pos[2 * p + 1] : neg[2 * (p - 16) + 1];
        Abase = lcs + (size_t)i0 * Ll * Dd + kh * 1024;
        Bbase = lcs + (size_t)i1 * Ll * Dd + kh * 1024;
        out = (kh ? g_dotL1 : g_dotL0) + (size_t)p * Ll * Ll;
        mode = 1;
    }
    Bbase += (size_t)colTile * Dd;

    __shared__ uint4 smBuf[2 * STAGE_BYTES / 16];
    __shared__ float rnAs[128];
    __shared__ float rnBs[64];
    char* smc = (char*)smBuf;
    uint32_t smemBase = (uint32_t)__cvta_generic_to_shared(smc);

    int lane = tid & 31;
    int warp = tid >> 5;
    int wm = warp >> 1;
    int wn = warp & 1;

    int aRow0 = tid >> 2,            aKg0 = tid & 3;
    int aRow1 = (tid + 256) >> 2,    aKg1 = tid & 3;
    int bRow  = tid >> 2,            bKg  = tid & 3;

    float acc[2][4][4];
#pragma unroll
    for (int i = 0; i < 2; ++i)
#pragma unroll
        for (int j = 0; j < 4; ++j)
#pragma unroll
            for (int q2 = 0; q2 < 4; ++q2) acc[i][j][q2] = 0.0f;

    float sqA0 = 0.0f, sqA1 = 0.0f, sqB = 0.0f;
    float4 bufA[2][2], bufB[2];

    const float* pA0 = Abase + (size_t)aRow0 * Dd + aKg0 * 8;
    const float* pA1 = Abase + (size_t)aRow1 * Dd + aKg1 * 8;
    const float* pB  = Bbase + (size_t)bRow  * Dd + bKg  * 8;

    bufA[0][0] = *(const float4*)(pA0);
    bufA[0][1] = *(const float4*)(pA0 + 4);
    bufA[1][0] = *(const float4*)(pA1);
    bufA[1][1] = *(const float4*)(pA1 + 4);
    bufB[0]    = *(const float4*)(pB);
    bufB[1]    = *(const float4*)(pB + 4);

    {
        const float* fa0 = (const float*)&bufA[0][0];
        const float* fa1 = (const float*)&bufA[1][0];
        const float* fbb = (const float*)&bufB[0];
#pragma unroll
        for (int q2 = 0; q2 < 8; ++q2) {
            sqA0 = fmaf(fa0[q2], fa0[q2], sqA0);
            sqA1 = fmaf(fa1[q2], fa1[q2], sqA1);
            sqB  = fmaf(fbb[q2], fbb[q2], sqB);
        }
        uint4 v;
        v.x = pk_bf2(fa0[0], fa0[1]); v.y = pk_bf2(fa0[2], fa0[3]);
        v.z = pk_bf2(fa0[4], fa0[5]); v.w = pk_bf2(fa0[6], fa0[7]);
        *(uint4*)(smc + swz(aRow0, aKg0 * 8)) = v;
        v.x = pk_bf2(fa1[0], fa1[1]); v.y = pk_bf2(fa1[2], fa1[3]);
        v.z = pk_bf2(fa1[4], fa1[5]); v.w = pk_bf2(fa1[6], fa1[7]);
        *(uint4*)(smc + swz(aRow1, aKg1 * 8)) = v;
        v.x = pk_bf2(fbb[0], fbb[1]); v.y = pk_bf2(fbb[2], fbb[3]);
        v.z = pk_bf2(fbb[4], fbb[5]); v.w = pk_bf2(fbb[6], fbb[7]);
        *(uint4*)(smc + 8192 + swz(bRow, bKg * 8)) = v;
    }
    __syncthreads();

    int grp = lane >> 3, r8 = lane & 7;
    uint32_t aRowL = (uint32_t)(r8 + (grp & 1) * 8);
    uint32_t aColL = (uint32_t)((grp >> 1) * 8);
    uint32_t bRowL = (uint32_t)(r8 + (grp >> 1) * 8);
    uint32_t bColL = (uint32_t)((grp & 1) * 8);

    for (int kt = 0; kt < KSTEPS; ++kt) {
        if (kt + 1 < KSTEPS) {
            int k0 = (kt + 1) * 32;
            bufA[0][0] = *(const float4*)(pA0 + k0);
            bufA[0][1] = *(const float4*)(pA0 + k0 + 4);
            bufA[1][0] = *(const float4*)(pA1 + k0);
            bufA[1][1] = *(const float4*)(pA1 + k0 + 4);
            bufB[0]    = *(const float4*)(pB + k0);
            bufB[1]    = *(const float4*)(pB + k0 + 4);
        }

        uint32_t stBase = smemBase + (uint32_t)(kt & 1) * STAGE_BYTES;
#pragma unroll
        for (int ks = 0; ks < 2; ++ks) {
            int k0 = ks * 16;
            uint32_t afr[2][4];
#pragma unroll
            for (int tm = 0; tm < 2; ++tm) {
                uint32_t m0 = (uint32_t)(wm * 32 + tm * 16);
                uint32_t addrA = stBase + swz(m0 + aRowL, (uint32_t)k0 + aColL);
                ldsm4(addrA, afr[tm][0], afr[tm][1], afr[tm][2], afr[tm][3]);
            }
            uint32_t bfr[2][4];
#pragma unroll
            for (int tb = 0; tb < 2; ++tb) {
                uint32_t n0 = (uint32_t)(wn * 32 + tb * 16);
                uint32_t addrB = stBase + 8192u + swz(n0 + bRowL, (uint32_t)k0 + bColL);
                ldsm4(addrB, bfr[tb][0], bfr[tb][1], bfr[tb][2], bfr[tb][3]);
            }
#pragma unroll
            for (int tm = 0; tm < 2; ++tm)
#pragma unroll
                for (int tn = 0; tn < 4; ++tn) {
                    int tb = tn >> 1, wh = tn & 1;
                    mma16816(acc[tm][tn], afr[tm], bfr[tb][wh * 2], bfr[tb][wh * 2 + 1]);
                }
        }

        if (kt + 1 < KSTEPS) {
            char* nst = smc + ((kt + 1) & 1) * STAGE_BYTES;
            const float* fa0 = (const float*)&bufA[0][0];
            const float* fa1 = (const float*)&bufA[1][0];
            const float* fbb = (const float*)&bufB[0];
#pragma unroll
            for (int q2 = 0; q2 < 8; ++q2) {
                sqA0 = fmaf(fa0[q2], fa0[q2], sqA0);
                sqA1 = fmaf(fa1[q2], fa1[q2], sqA1);
                sqB  = fmaf(fbb[q2], fbb[q2], sqB);
            }
            uint4 v;
            v.x = pk_bf2(fa0[0], fa0[1]); v.y = pk_bf2(fa0[2], fa0[3]);
            v.z = pk_bf2(fa0[4], fa0[5]); v.w = pk_bf2(fa0[6], fa0[7]);
            *(uint4*)(nst + swz(aRow0, aKg0 * 8)) = v;
            v.x = pk_bf2(fa1[0], fa1[1]); v.y = pk_bf2(fa1[2], fa1[3]);
            v.z = pk_bf2(fa1[4], fa1[5]); v.w = pk_bf2(fa1[6], fa1[7]);
            *(uint4*)(nst + swz(aRow1, aKg1 * 8)) = v;
            v.x = pk_bf2(fbb[0], fbb[1]); v.y = pk_bf2(fbb[2], fbb[3]);
            v.z = pk_bf2(fbb[4], fbb[5]); v.w = pk_bf2(fbb[6], fbb[7]);
            *(uint4*)(nst + 8192 + swz(bRow, bKg * 8)) = v;
        }
        __syncthreads();
    }

    sqA0 += __shfl_xor_sync(0xffffffffu, sqA0, 1);
    sqA0 += __shfl_xor_sync(0xffffffffu, sqA0, 2);
    sqA1 += __shfl_xor_sync(0xffffffffu, sqA1, 1);
    sqA1 += __shfl_xor_sync(0xffffffffu, sqA1, 2);
    sqB  += __shfl_xor_sync(0xffffffffu, sqB, 1);
    sqB  += __shfl_xor_sync(0xffffffffu, sqB, 2);

    if (mode == 1) {
        if ((tid & 3) == 0) {
            g_nAL[kh][p_idx][aRow0] = sqA0;
            g_nAL[kh][p_idx][aRow1] = sqA1;
            g_nBL[kh][p_idx][colTile + bRow] = sqB;
        }
        int g8 = lane >> 2, tq = lane & 3;
#pragma unroll
        for (int tm = 0; tm < 2; ++tm) {
            int row0 = wm * 32 + tm * 16 + g8;
            int row1 = row0 + 8;
#pragma unroll
            for (int tn = 0; tn < 4; ++tn) {
                int col = colTile + wn * 32 + tn * 8 + 2 * tq;
                *(float2*)(out + row0 * Ll + col) =
                    make_float2(acc[tm][tn][0], acc[tm][tn][1]);
                *(float2*)(out + row1 * Ll + col) =
                    make_float2(acc[tm][tn][2], acc[tm][tn][3]);
            }
        }
        return;
    }

    if ((tid & 3) == 0) {
        rnAs[aRow0] = rsqrtf(sqA0);
        rnAs[aRow1] = rsqrtf(sqA1);
        rnBs[bRow]  = rsqrtf(sqB);
    }
    __syncthreads();

    int g8 = lane >> 2, tq = lane & 3;
#pragma unroll
    for (int tm = 0; tm < 2; ++tm) {
        int row0 = wm * 32 + tm * 16 + g8;
        int row1 = row0 + 8;
        float ra0 = rnAs[row0], ra1 = rnAs[row1];
#pragma unroll
        for (int tn = 0; tn < 4; ++tn) {
            int lcol = wn * 32 + tn * 8 + 2 * tq;
            int col = colTile + lcol;
            float rb0 = rnBs[lcol], rb1 = rnBs[lcol + 1];
            float v00 = acc[tm][tn][0] * ra0 * rb0 * FSD_SCALE;
            float v01 = acc[tm][tn][1] * ra0 * rb1 * FSD_SCALE;
            float v10 = acc[tm][tn][2] * ra1 * rb0 * FSD_SCALE;
            float v11 = acc[tm][tn][3] * ra1 * rb1 * FSD_SCALE;
            *(float2*)(out + row0 * Ll + col) = make_float2(v00, v01);
            *(float2*)(out + row1 * Ll + col) = make_float2(v10, v11);
        }
    }
}

// ---------------------------------------------------------------------------
// DP (4-warp wavefront, 1 row/thread) + small losses + final combine.
// Blocks 0..31 FSD, 32..63 LCS (with fused split-K epilogue), 64..95 small.
// ---------------------------------------------------------------------------
__device__ __forceinline__ float ex2f(float x) {
    float y; asm("ex2.approx.f32 %0, %1;" : "=f"(y) : "f"(x)); return y;
}
__device__ __forceinline__ float lg2f(float x) {
    float y; asm("lg2.approx.f32 %0, %1;" : "=f"(y) : "f"(x)); return y;
}

__device__ __forceinline__ void block_done(float* out) {
    __threadfence();
    unsigned v = atomicAdd(&g_done, 1u);
    if (v == 95u) {
        volatile float* gp = g_partial;
        float cls    = gp[0] / 32.0f;
        float guide  = gp[1] / 32.0f;
        float feat   = gp[2] / 32.0f;
        float sparse = gp[3] / 64.0f;
        float acm = cls + guide + 5e-5f * feat + 2e-4f * sparse;
        float lcs_loss = (gp[5] - gp[4]) / 16.0f;
        float fsd_loss = (gp[7] - gp[6]) / 16.0f;
        out[0] = acm + 0.1f * lcs_loss + 0.1f * fsd_loss;
        g_done = 0;
    }
}

__global__ void k_dpall(const float* __restrict__ xi,
                        const float* __restrict__ xc,
                        const float* __restrict__ xb,
                        const float* __restrict__ vid,
                        const float* __restrict__ att,
                        const float* __restrict__ fi,
                        const float* __restrict__ fc,
                        const float* __restrict__ fb,
                        const float* __restrict__ cas,
                        float* __restrict__ outp) {
    extern __shared__ float dsm[];     // Ms[16384] (+ Gs[16384] for FSD)
    __shared__ float bnd[2][4];
    int b = blockIdx.x;
    int tid = threadIdx.x;

    if (b >= 64) {
        // -------- small losses --------
        __shared__ float red[128];
        int bb = b - 64;
        float guide = 0.0f, sparse = 0.0f, si2 = 0.0f, sc2 = 0.0f, sb2 = 0.0f;
        for (int tt = tid; tt < Tt; tt += 128) {
            float cas20 = cas[((size_t)bb * Tt + tt) * (NCLS + 1) + NCLS];
            float a0 = att[((size_t)bb * Tt + tt) * 3 + 0];
            float a1 = att[((size_t)bb * Tt + tt) * 3 + 1];
            guide  += fabsf(1.0f - cas20 - a0);
            sparse += a0 + a1;
        }
        for (int k = tid; k < Dd; k += 128) {
            float v1 = fi[(size_t)bb * Dd + k];
            float v2 = fc[(size_t)bb * Dd + k];
            float v3 = fb[(size_t)bb * Dd + k];
            si2 += v1 * v1; sc2 += v2 * v2; sb2 += v3 * v3;
        }
        float vals[5] = {guide, sparse, si2, sc2, sb2};
#pragma unroll
        for (int v = 0; v < 5; ++v) {
            red[tid] = vals[v];
            __syncthreads();
            for (int s = 64; s > 0; s >>= 1) {
                if (tid < s) red[tid] += red[tid + s];
                __syncthreads();
            }
            vals[v] = red[0];
            __syncthreads();
        }
        if (tid == 0) {
            float ni = sqrtf(vals[2]);
            float nc = sqrtf(vals[3]);
            float nb = sqrtf(vals[4]);
            float f1 = fmaxf(50.0f - ni + nc, 0.0f);
            float f2 = fmaxf(50.0f - nc + nb, 0.0f);
            float feat = (f1 + f2 + nb) * (f1 + f2 + nb);
            float sv = 0.0f, s_i = 0.0f, s_c = 0.0f;
            for (int c = 0; c < NCLS; ++c) {
                float l = vid[bb * NCLS + c];
                sv  += l;
                s_i += l * logf(xi[bb * (NCLS + 1) + c] + 1e-45f);
                s_c += l * logf(xc[bb * (NCLS + 1) + c] + 1e-45f);
            }
            float inst_b = -s_i / sv;
            float cont_b = -(s_c + logf(xc[bb * (NCLS + 1) + NCLS] + 1e-45f)) / (sv + 1.0f);
            float back_b = -logf(xb[bb * (NCLS + 1) + NCLS] + 1e-45f);
            atomicAdd(&g_partial[0], inst_b + cont_b + back_b);
            atomicAdd(&g_partial[1], vals[0]);
            atomicAdd(&g_partial[2], feat);
            atomicAdd(&g_partial[3], vals[1]);
            block_done(outp);
        }
        return;
    }

    bool isFsd = (b < 32);
    int pair = isFsd ? b : b - 32;
    float* Ms = dsm;
    float* Gs = dsm + 16384;

    if (isFsd) {
        const float* Mb = g_sim_m + (size_t)pair * 16384;
        const float* Gb = g_sim_g + (size_t)pair * 16384;
        for (int idx = tid * 4; idx < 16384; idx += 512) {
            *(float4*)(Ms + idx) = *(const float4*)(Mb + idx);
            *(float4*)(Gs + idx) = *(const float4*)(Gb + idx);
        }
    } else {
        // fused LCS epilogue: combine split-K dots, normalize, transform
        __shared__ float rA[128], rB[128];
        rA[tid] = rsqrtf(g_nAL[0][pair][tid] + g_nAL[1][pair][tid]);
        rB[tid] = rsqrtf(g_nBL[0][pair][tid] + g_nBL[1][pair][tid]);
        __syncthreads();
        const float* d0 = g_dotL0 + (size_t)pair * 16384;
        const float* d1 = g_dotL1 + (size_t)pair * 16384;
        for (int idx = tid * 4; idx < 16384; idx += 512) {
            float4 a4 = *(const float4*)(d0 + idx);
            float4 b4 = *(const float4*)(d1 + idx);
            int row = idx >> 7, col = idx & 127;
            float ra = rA[row];
            float4 r;
            r.x = fmaxf(0.0f, (a4.x + b4.x) * ra * rB[col + 0] - 0.8f) * 5.0f;
            r.y = fmaxf(0.0f, (a4.y + b4.y) * ra * rB[col + 1] - 0.8f) * 5.0f;
            r.z = fmaxf(0.0f, (a4.z + b4.z) * ra * rB[col + 2] - 0.8f) * 5.0f;
            r.w = fmaxf(0.0f, (a4.w + b4.w) * ra * rB[col + 3] - 0.8f) * 5.0f;
            *(float4*)(Ms + idx) = r;
        }
    }
    if (tid < 8) bnd[tid >> 2][tid & 3] = 0.0f;
    __syncthreads();

    // 4-warp wavefront: thread tid owns row tid; cell (tid, s - tid).
    int w = tid >> 5, lane = tid & 31;
    int wlo = w * 32, whi = w * 32 + 159;   // warp activity window [wlo, whi)
    const float* mrow = Ms + tid * 127;     // mrow[s] = M[tid][s - tid]
    const float* grow = Gs + tid * 127;

    float v = 0.0f, d = 0.0f;

    if (isFsd) {
        for (int s = 0; s < 255; ++s) {
            if (s >= wlo && s < whi) {
                float au = __shfl_up_sync(0xffffffffu, v, 1);
                float a;
                if (lane == 0) a = (w > 0) ? bnd[(s + 1) & 1][w - 1] : 0.0f;
                else           a = au;
                if ((unsigned)(s - tid) < 128u) {
                    float m = mrow[s], g = grow[s];
                    float x1 = g + a;
                    float x2 = g + v;
                    float mx = fmaxf(fmaxf(d, x1), x2);
                    float e = ex2f(d - mx) + ex2f(x1 - mx) + ex2f(x2 - mx);
                    v = m + mx + lg2f(e);
                }
                d = a;
                if (lane == 31) bnd[s & 1][w] = v;
            }
            __syncthreads();
        }
        if (tid == 127) {
            atomicAdd(&g_partial[pair < 16 ? 6 : 7], v * FSD_UNSCALE);
            block_done(outp);
        }
    } else {
        for (int s = 0; s < 255; ++s) {
            if (s >= wlo && s < whi) {
                float au = __shfl_up_sync(0xffffffffu, v, 1);
                float a;
                if (lane == 0) a = (w > 0) ? bnd[(s + 1) & 1][w - 1] : 0.0f;
                else           a = au;
                if ((unsigned)(s - tid) < 128u) {
                    float sv = mrow[s];
                    v = (sv > 0.5f) ? d + sv : fmaxf(a, v);
                }
                d = a;
                if (lane == 31) bnd[s & 1][w] = v;
            }
            __syncthreads();
        }
        if (tid == 127) {
            atomicAdd(&g_partial[pair < 16 ? 4 : 5], v);
            block_done(outp);
        }
    }
}

// ---------------------------------------------------------------------------
// Launch
// ---------------------------------------------------------------------------
extern "C" void kernel_launch(void* const* d_in, const int* in_sizes, int n_in,
                              void* d_out, int out_size) {
    const float* xi  = (const float*)d_in[0];
    const float* xc  = (const float*)d_in[1];
    const float* xb  = (const float*)d_in[2];
    const float* vid = (const float*)d_in[3];
    const float* att = (const float*)d_in[4];
    const float* fi  = (const float*)d_in[5];
    const float* fc  = (const float*)d_in[6];
    const float* fb  = (const float*)d_in[7];
    const float* cas = (const float*)d_in[8];
    const float* lcs = (const float*)d_in[9];
    const float* act = (const float*)d_in[10];
    const float* bak = (const float*)d_in[11];
    const int*   pos = (const int*)d_in[12];
    const int*   neg = (const int*)d_in[13];
    float* out = (float*)d_out;

    const int dp_smem = 2 * 16384 * (int)sizeof(float);   // 128 KB
    cudaFuncSetAttribute(k_dpall, cudaFuncAttributeMaxDynamicSharedMemorySize, dp_smem);

    k_gemm<<<256, 256>>>(lcs, act, bak, pos, neg);
    k_dpall<<<96, 128, dp_smem>>>(xi, xc, xb, vid, att, fi, fc, fb, cas, out);
}